// round 4
// baseline (speedup 1.0000x reference)
#include <cuda_runtime.h>
#include <math.h>

#define Bc  8
#define Lc  1024
#define Dc  1024
#define Hc  16
#define HDc 64
#define BHc (Bc*Hc)   // 128
#define Mc  (Bc*Lc)   // 8192

// Scratch (allocation-free rule: __device__ globals)
__device__ float g_q [BHc*Lc*HDc];
__device__ float g_k [BHc*Lc*HDc];
__device__ float g_v [BHc*Lc*HDc];
__device__ float g_q2[BHc*Lc*HDc];
__device__ float g_k2[BHc*Lc*HDc];
__device__ float g_s [134217728];   // B*H*L*L scores/probs (512MB)

// ---------------------------------------------------------------------------
// Kernel 1: fused projections. grid = (8, 64, 5), block = 256.
// C[m][n] = A[m][:] @ W[:][n] + bias[n], scattered to [B,H,L,HD] layout.
// ---------------------------------------------------------------------------
__global__ __launch_bounds__(256) void proj_kernel(
    const float* __restrict__ hidden, const float* __restrict__ source,
    const float* __restrict__ Wq,  const float* __restrict__ bq,
    const float* __restrict__ Wk,  const float* __restrict__ bk,
    const float* __restrict__ Wv,  const float* __restrict__ bv,
    const float* __restrict__ Wq2, const float* __restrict__ bq2,
    const float* __restrict__ Wk2, const float* __restrict__ bk2)
{
    __shared__ __align__(16) float As[16][128];
    __shared__ __align__(16) float Bs[16][128];

    int w = blockIdx.z;
    const float* A = (w == 4) ? source : hidden;
    const float* W; const float* bias; float* out;
    if (w == 0)      { W = Wq;  bias = bq;  out = g_q;  }
    else if (w == 1) { W = Wk;  bias = bk;  out = g_k;  }
    else if (w == 2) { W = Wv;  bias = bv;  out = g_v;  }
    else if (w == 3) { W = Wq2; bias = bq2; out = g_q2; }
    else             { W = Wk2; bias = bk2; out = g_k2; }

    int mBase = blockIdx.y * 128;
    int nBase = blockIdx.x * 128;
    int tid = threadIdx.x;
    int tx = tid & 15, ty = tid >> 4;

    float acc[8][8];
    #pragma unroll
    for (int i = 0; i < 8; i++)
        #pragma unroll
        for (int j = 0; j < 8; j++) acc[i][j] = 0.f;

    for (int k0 = 0; k0 < Dc; k0 += 16) {
        #pragma unroll
        for (int i = 0; i < 2; i++) {
            int lin = tid + i * 256;
            int r  = lin >> 2;
            int c4 = (lin & 3) << 2;
            float4 va = *(const float4*)&A[(size_t)(mBase + r) * Dc + k0 + c4];
            As[c4+0][r] = va.x; As[c4+1][r] = va.y; As[c4+2][r] = va.z; As[c4+3][r] = va.w;
            int rb = lin >> 5;
            int cb = (lin & 31) << 2;
            *(float4*)&Bs[rb][cb] = *(const float4*)&W[(size_t)(k0 + rb) * Dc + nBase + cb];
        }
        __syncthreads();
        #pragma unroll
        for (int kk = 0; kk < 16; kk++) {
            float a[8], bb[8];
            float4 t;
            t = *(const float4*)&As[kk][ty*4];      a[0]=t.x; a[1]=t.y; a[2]=t.z; a[3]=t.w;
            t = *(const float4*)&As[kk][64+ty*4];   a[4]=t.x; a[5]=t.y; a[6]=t.z; a[7]=t.w;
            t = *(const float4*)&Bs[kk][tx*4];      bb[0]=t.x; bb[1]=t.y; bb[2]=t.z; bb[3]=t.w;
            t = *(const float4*)&Bs[kk][64+tx*4];   bb[4]=t.x; bb[5]=t.y; bb[6]=t.z; bb[7]=t.w;
            #pragma unroll
            for (int i = 0; i < 8; i++)
                #pragma unroll
                for (int j = 0; j < 8; j++) acc[i][j] += a[i] * bb[j];
        }
        __syncthreads();
    }

    // Epilogue: n -> (head, hd). nBase multiple of 128 => col groups map to heads h0, h0+1.
    int h0 = nBase >> 6;
    float4 b0 = *(const float4*)&bias[nBase + tx*4];
    float4 b1 = *(const float4*)&bias[nBase + 64 + tx*4];
    #pragma unroll
    for (int i = 0; i < 8; i++) {
        int row = (i < 4) ? (ty*4 + i) : (64 + ty*4 + (i - 4));
        int m = mBase + row;
        int b_ = m >> 10, l = m & 1023;
        float4 o0 = make_float4(acc[i][0]+b0.x, acc[i][1]+b0.y, acc[i][2]+b0.z, acc[i][3]+b0.w);
        float4 o1 = make_float4(acc[i][4]+b1.x, acc[i][5]+b1.y, acc[i][6]+b1.z, acc[i][7]+b1.w);
        *(float4*)&out[(size_t)((b_*Hc + h0    ) * Lc + l) * HDc + tx*4] = o0;
        *(float4*)&out[(size_t)((b_*Hc + h0 + 1) * Lc + l) * HDc + tx*4] = o1;
    }
}

// ---------------------------------------------------------------------------
// Kernel 2: scores. grid = (8, 8, 128), block = 256.
// S[bh][m][n] = (Q[m]·K[n] + Q2[m]·K2[n]) * scale + mask[b][n]
// ---------------------------------------------------------------------------
__global__ __launch_bounds__(256) void scores_kernel(const float* __restrict__ mask)
{
    __shared__ __align__(16) float As[16][128];
    __shared__ __align__(16) float Bs[16][128];

    int bh = blockIdx.z;
    int b_ = bh >> 4;
    const float* Q  = g_q  + (size_t)bh * Lc * HDc;
    const float* Km = g_k  + (size_t)bh * Lc * HDc;
    const float* Q2 = g_q2 + (size_t)bh * Lc * HDc;
    const float* K2 = g_k2 + (size_t)bh * Lc * HDc;
    float* S = g_s + (size_t)bh * Lc * Lc;

    int mBase = blockIdx.y * 128, nBase = blockIdx.x * 128;
    int tid = threadIdx.x, tx = tid & 15, ty = tid >> 4;

    float acc[8][8];
    #pragma unroll
    for (int i = 0; i < 8; i++)
        #pragma unroll
        for (int j = 0; j < 8; j++) acc[i][j] = 0.f;

    #pragma unroll
    for (int phase = 0; phase < 2; phase++) {
        const float* Ap = phase ? Q2 : Q;
        const float* Bp = phase ? K2 : Km;
        for (int k0 = 0; k0 < HDc; k0 += 16) {
            #pragma unroll
            for (int i = 0; i < 2; i++) {
                int lin = tid + i * 256;
                int r  = lin >> 2;
                int c4 = (lin & 3) << 2;
                float4 va = *(const float4*)&Ap[(size_t)(mBase + r) * HDc + k0 + c4];
                As[c4+0][r] = va.x; As[c4+1][r] = va.y; As[c4+2][r] = va.z; As[c4+3][r] = va.w;
                float4 vb = *(const float4*)&Bp[(size_t)(nBase + r) * HDc + k0 + c4];
                Bs[c4+0][r] = vb.x; Bs[c4+1][r] = vb.y; Bs[c4+2][r] = vb.z; Bs[c4+3][r] = vb.w;
            }
            __syncthreads();
            #pragma unroll
            for (int kk = 0; kk < 16; kk++) {
                float a[8], bb[8];
                float4 t;
                t = *(const float4*)&As[kk][ty*4];      a[0]=t.x; a[1]=t.y; a[2]=t.z; a[3]=t.w;
                t = *(const float4*)&As[kk][64+ty*4];   a[4]=t.x; a[5]=t.y; a[6]=t.z; a[7]=t.w;
                t = *(const float4*)&Bs[kk][tx*4];      bb[0]=t.x; bb[1]=t.y; bb[2]=t.z; bb[3]=t.w;
                t = *(const float4*)&Bs[kk][64+tx*4];   bb[4]=t.x; bb[5]=t.y; bb[6]=t.z; bb[7]=t.w;
                #pragma unroll
                for (int i = 0; i < 8; i++)
                    #pragma unroll
                    for (int j = 0; j < 8; j++) acc[i][j] += a[i] * bb[j];
            }
            __syncthreads();
        }
    }

    const float scale = 0.125f;   // 1/sqrt(64)
    float4 mk0 = *(const float4*)&mask[b_*Lc + nBase + tx*4];
    float4 mk1 = *(const float4*)&mask[b_*Lc + nBase + 64 + tx*4];
    #pragma unroll
    for (int i = 0; i < 8; i++) {
        int row = (i < 4) ? (ty*4 + i) : (64 + ty*4 + (i - 4));
        int m = mBase + row;
        float4 s0 = make_float4(acc[i][0]*scale + mk0.x, acc[i][1]*scale + mk0.y,
                                acc[i][2]*scale + mk0.z, acc[i][3]*scale + mk0.w);
        float4 s1 = make_float4(acc[i][4]*scale + mk1.x, acc[i][5]*scale + mk1.y,
                                acc[i][6]*scale + mk1.z, acc[i][7]*scale + mk1.w);
        *(float4*)&S[(size_t)m * Lc + nBase + tx*4]      = s0;
        *(float4*)&S[(size_t)m * Lc + nBase + 64 + tx*4] = s1;
    }
}

// ---------------------------------------------------------------------------
// Kernel 3: in-place softmax over rows of 1024. grid = 131072, block = 256.
// ---------------------------------------------------------------------------
__global__ __launch_bounds__(256) void softmax_kernel()
{
    size_t row = blockIdx.x;
    float* p = g_s + row * Lc;
    int tid = threadIdx.x;
    int lane = tid & 31, wid = tid >> 5;
    __shared__ float red[8];

    float4 v = *(float4*)&p[tid * 4];
    float m = fmaxf(fmaxf(v.x, v.y), fmaxf(v.z, v.w));
    #pragma unroll
    for (int o = 16; o > 0; o >>= 1) m = fmaxf(m, __shfl_xor_sync(0xffffffffu, m, o));
    if (lane == 0) red[wid] = m;
    __syncthreads();
    if (tid == 0) {
        float mm = red[0];
        #pragma unroll
        for (int i = 1; i < 8; i++) mm = fmaxf(mm, red[i]);
        red[0] = mm;
    }
    __syncthreads();
    m = red[0];
    __syncthreads();

    v.x = expf(v.x - m); v.y = expf(v.y - m);
    v.z = expf(v.z - m); v.w = expf(v.w - m);
    float s = v.x + v.y + v.z + v.w;
    #pragma unroll
    for (int o = 16; o > 0; o >>= 1) s += __shfl_xor_sync(0xffffffffu, s, o);
    if (lane == 0) red[wid] = s;
    __syncthreads();
    if (tid == 0) {
        float ss = red[0];
        #pragma unroll
        for (int i = 1; i < 8; i++) ss += red[i];
        red[0] = ss;
    }
    __syncthreads();
    float inv = 1.f / red[0];
    v.x *= inv; v.y *= inv; v.z *= inv; v.w *= inv;
    *(float4*)&p[tid * 4] = v;
}

// ---------------------------------------------------------------------------
// Kernel 4: ctx = P @ V, write [B,L,D]. grid = (1, 8, 128), block = 256.
// ---------------------------------------------------------------------------
__global__ __launch_bounds__(256) void pv_kernel(float* __restrict__ out)
{
    __shared__ __align__(16) float Ps[16][128];
    __shared__ __align__(16) float Vs[16][64];

    int bh = blockIdx.z;
    int b_ = bh >> 4, h = bh & 15;
    const float* P = g_s + (size_t)bh * Lc * Lc;
    const float* V = g_v + (size_t)bh * Lc * HDc;
    int mBase = blockIdx.y * 128;
    int tid = threadIdx.x, tx = tid & 15, ty = tid >> 4;

    float acc[8][4];
    #pragma unroll
    for (int i = 0; i < 8; i++)
        #pragma unroll
        for (int j = 0; j < 4; j++) acc[i][j] = 0.f;

    for (int k0 = 0; k0 < Lc; k0 += 16) {
        #pragma unroll
        for (int i = 0; i < 2; i++) {
            int lin = tid + i * 256;
            int r  = lin >> 2;
            int c4 = (lin & 3) << 2;
            float4 vp = *(const float4*)&P[(size_t)(mBase + r) * Lc + k0 + c4];
            Ps[c4+0][r] = vp.x; Ps[c4+1][r] = vp.y; Ps[c4+2][r] = vp.z; Ps[c4+3][r] = vp.w;
        }
        {
            int r = tid >> 4, c4 = (tid & 15) << 2;
            *(float4*)&Vs[r][c4] = *(const float4*)&V[(size_t)(k0 + r) * HDc + c4];
        }
        __syncthreads();
        #pragma unroll
        for (int kk = 0; kk < 16; kk++) {
            float a[8];
            float4 t;
            t = *(const float4*)&Ps[kk][ty*4];     a[0]=t.x; a[1]=t.y; a[2]=t.z; a[3]=t.w;
            t = *(const float4*)&Ps[kk][64+ty*4];  a[4]=t.x; a[5]=t.y; a[6]=t.z; a[7]=t.w;
            float4 bv4 = *(const float4*)&Vs[kk][tx*4];
            float bb[4] = {bv4.x, bv4.y, bv4.z, bv4.w};
            #pragma unroll
            for (int i = 0; i < 8; i++)
                #pragma unroll
                for (int j = 0; j < 4; j++) acc[i][j] += a[i] * bb[j];
        }
        __syncthreads();
    }

    #pragma unroll
    for (int i = 0; i < 8; i++) {
        int row = (i < 4) ? (ty*4 + i) : (64 + ty*4 + (i - 4));
        int l = mBase + row;
        float4 o = make_float4(acc[i][0], acc[i][1], acc[i][2], acc[i][3]);
        *(float4*)&out[(size_t)(b_*Lc + l) * Dc + h*HDc + tx*4] = o;
    }
}

// ---------------------------------------------------------------------------
extern "C" void kernel_launch(void* const* d_in, const int* in_sizes, int n_in,
                              void* d_out, int out_size)
{
    (void)in_sizes; (void)n_in; (void)out_size;
    const float* hidden = (const float*)d_in[0];
    const float* mask   = (const float*)d_in[1];
    const float* source = (const float*)d_in[2];
    const float* Wq  = (const float*)d_in[3];  const float* bq  = (const float*)d_in[4];
    const float* Wk  = (const float*)d_in[5];  const float* bk  = (const float*)d_in[6];
    const float* Wv  = (const float*)d_in[7];  const float* bv  = (const float*)d_in[8];
    const float* Wq2 = (const float*)d_in[9];  const float* bq2 = (const float*)d_in[10];
    const float* Wk2 = (const float*)d_in[11]; const float* bk2 = (const float*)d_in[12];
    float* out = (float*)d_out;

    dim3 g1(8, 64, 5);
    proj_kernel<<<g1, 256>>>(hidden, source, Wq, bq, Wk, bk, Wv, bv, Wq2, bq2, Wk2, bk2);
    dim3 g2(8, 8, 128);
    scores_kernel<<<g2, 256>>>(mask);
    softmax_kernel<<<131072, 256>>>();
    dim3 g4(1, 8, 128);
    pv_kernel<<<g4, 256>>>(out);
}

// round 6
// speedup vs baseline: 2.6146x; 2.6146x over previous
#include <cuda_runtime.h>
#include <cuda_bf16.h>
#include <stdint.h>
#include <math.h>

#define Dc 1024

// ------------------------- scratch (__device__ globals) ---------------------
__device__ __align__(128) __nv_bfloat16 g_hid_hi[8192*1024];
__device__ __align__(128) __nv_bfloat16 g_hid_lo[8192*1024];
__device__ __align__(128) __nv_bfloat16 g_src_hi[8192*1024];
__device__ __align__(128) __nv_bfloat16 g_src_lo[8192*1024];
__device__ __align__(128) __nv_bfloat16 g_wt_hi[5*1024*1024];
__device__ __align__(128) __nv_bfloat16 g_wt_lo[5*1024*1024];
__device__ __align__(128) __nv_bfloat16 g_qq2_hi[(size_t)128*1024*128];
__device__ __align__(128) __nv_bfloat16 g_qq2_lo[(size_t)128*1024*128];
__device__ __align__(128) __nv_bfloat16 g_kk2_hi[(size_t)128*1024*128];
__device__ __align__(128) __nv_bfloat16 g_kk2_lo[(size_t)128*1024*128];
__device__ __align__(128) __nv_bfloat16 g_vt_hi[(size_t)128*64*1024];
__device__ __align__(128) __nv_bfloat16 g_vt_lo[(size_t)128*64*1024];
__device__ __align__(128) float          g_scores[(size_t)134217728];
__device__ __align__(128) __nv_bfloat16 g_p_hi[(size_t)134217728];
__device__ __align__(128) __nv_bfloat16 g_p_lo[(size_t)134217728];

// ------------------------- warp-MMA helpers ----------------------------------
__device__ __forceinline__ uint32_t smem_u32(const void* p) {
    uint32_t a;
    asm("{ .reg .u64 t; cvta.to.shared.u64 t, %1; cvt.u32.u64 %0, t; }" : "=r"(a) : "l"(p));
    return a;
}
__device__ __forceinline__ void ldsm4(uint32_t* r, uint32_t addr) {
    asm volatile("ldmatrix.sync.aligned.m8n8.x4.shared.b16 {%0,%1,%2,%3}, [%4];"
        : "=r"(r[0]), "=r"(r[1]), "=r"(r[2]), "=r"(r[3]) : "r"(addr));
}
__device__ __forceinline__ void mma16816(float* c, const uint32_t* a, uint32_t b0, uint32_t b1) {
    asm volatile(
        "mma.sync.aligned.m16n8k16.row.col.f32.bf16.bf16.f32 "
        "{%0,%1,%2,%3}, {%4,%5,%6,%7}, {%8,%9}, {%0,%1,%2,%3};"
        : "+f"(c[0]), "+f"(c[1]), "+f"(c[2]), "+f"(c[3])
        : "r"(a[0]), "r"(a[1]), "r"(a[2]), "r"(a[3]), "r"(b0), "r"(b1));
}

// smem tile layout: rows of 40 bf16 (32 data + 8 pad) = 80B stride
#define TSTR 40
#define SA_HI 0
#define SA_LO 10240
#define SB_HI 20480
#define SB_LO 30720

__device__ __forceinline__ void load_tile128(char* sm, int off, const __nv_bfloat16* src,
                                             int ld, int k0, int tid) {
    #pragma unroll
    for (int i = 0; i < 2; i++) {
        int idx = tid + i * 256;
        int r = idx >> 2, c8 = (idx & 3) << 3;
        *(uint4*)(sm + off + (r * TSTR + c8) * 2) = *(const uint4*)(src + (size_t)r * ld + k0 + c8);
    }
}

// 3-pass (AhBh + AlBh + AhBl) 128x128 MMA over one BK=32 chunk already in smem.
__device__ __forceinline__ void mma_chunk_128x128(uint32_t smb, int wm, int wn, int lane,
                                                  float acc[2][8][4]) {
    int arow = (lane & 7) + ((lane >> 3) & 1) * 8;
    int acol = (lane >> 4) * 8;
    #pragma unroll
    for (int pass = 0; pass < 3; pass++) {
        uint32_t aB = smb + ((pass == 1) ? SA_LO : SA_HI);
        uint32_t bB = smb + ((pass == 2) ? SB_LO : SB_HI);
        #pragma unroll
        for (int ks = 0; ks < 2; ks++) {
            uint32_t af[2][4];
            #pragma unroll
            for (int mi = 0; mi < 2; mi++)
                ldsm4(af[mi], aB + (uint32_t)((wm*32 + mi*16 + arow) * TSTR + ks*16 + acol) * 2);
            #pragma unroll
            for (int nb = 0; nb < 4; nb++) {
                uint32_t bt[4];
                ldsm4(bt, bB + (uint32_t)((wn*64 + nb*16 + arow) * TSTR + ks*16 + acol) * 2);
                #pragma unroll
                for (int mi = 0; mi < 2; mi++) {
                    mma16816(acc[mi][nb*2],     af[mi], bt[0], bt[2]);
                    mma16816(acc[mi][nb*2 + 1], af[mi], bt[1], bt[3]);
                }
            }
        }
    }
}

// ------------------------- conversion kernels --------------------------------
__global__ __launch_bounds__(256) void split_acts(const float* __restrict__ in, int which)
{
    __nv_bfloat16* hi = which ? g_src_hi : g_hid_hi;
    __nv_bfloat16* lo = which ? g_src_lo : g_hid_lo;
    size_t i = ((size_t)blockIdx.x * 256 + threadIdx.x) * 4;
    float4 v = *(const float4*)(in + i);
    float x[4] = {v.x, v.y, v.z, v.w};
    #pragma unroll
    for (int j = 0; j < 4; j++) {
        __nv_bfloat16 h = __float2bfloat16(x[j]);
        hi[i + j] = h;
        lo[i + j] = __float2bfloat16(x[j] - __bfloat162float(h));
    }
}

__global__ __launch_bounds__(256) void split_wt(
    const float* __restrict__ Wq, const float* __restrict__ Wk, const float* __restrict__ Wv,
    const float* __restrict__ Wq2, const float* __restrict__ Wk2)
{
    __shared__ float t[32][33];
    int w = blockIdx.z;
    const float* W = (w==0)?Wq:(w==1)?Wk:(w==2)?Wv:(w==3)?Wq2:Wk2;
    int tx = threadIdx.x & 31, ty = threadIdx.x >> 5;
    int n0 = blockIdx.x * 32, k0 = blockIdx.y * 32;
    #pragma unroll
    for (int j = 0; j < 32; j += 8)
        t[ty + j][tx] = W[(size_t)(k0 + ty + j) * Dc + n0 + tx];
    __syncthreads();
    size_t woff = (size_t)w * Dc * Dc;
    #pragma unroll
    for (int j = 0; j < 32; j += 8) {
        float x = t[tx][ty + j];
        __nv_bfloat16 h = __float2bfloat16(x);
        size_t o = woff + (size_t)(n0 + ty + j) * Dc + k0 + tx;
        g_wt_hi[o] = h;
        g_wt_lo[o] = __float2bfloat16(x - __bfloat162float(h));
    }
}

// ------------------------- projection GEMM -----------------------------------
// grid (8, 64, 5), block 256. Tile 128(M) x 128(N), K=1024.
__global__ __launch_bounds__(256) void proj_gemm(
    const float* __restrict__ bq, const float* __restrict__ bk, const float* __restrict__ bv,
    const float* __restrict__ bq2, const float* __restrict__ bk2)
{
    __shared__ __align__(16) char sm[40960];
    uint32_t smb = smem_u32(sm);
    int w = blockIdx.z, nT = blockIdx.x, mT = blockIdx.y;
    const __nv_bfloat16* Ah = ((w == 4) ? g_src_hi : g_hid_hi) + (size_t)mT * 128 * Dc;
    const __nv_bfloat16* Al = ((w == 4) ? g_src_lo : g_hid_lo) + (size_t)mT * 128 * Dc;
    size_t woff = (size_t)w * Dc * Dc + (size_t)nT * 128 * Dc;
    const __nv_bfloat16* Bh = g_wt_hi + woff;
    const __nv_bfloat16* Bl = g_wt_lo + woff;
    const float* bias = (w==0)?bq:(w==1)?bk:(w==2)?bv:(w==3)?bq2:bk2;

    int tid = threadIdx.x, lane = tid & 31, wid = tid >> 5;
    int wm = wid & 3, wn = wid >> 2;

    float acc[2][8][4];
    #pragma unroll
    for (int a = 0; a < 2; a++)
        #pragma unroll
        for (int b = 0; b < 8; b++)
            #pragma unroll
            for (int c = 0; c < 4; c++) acc[a][b][c] = 0.f;

    for (int k0 = 0; k0 < Dc; k0 += 32) {
        load_tile128(sm, SA_HI, Ah, Dc, k0, tid);
        load_tile128(sm, SA_LO, Al, Dc, k0, tid);
        load_tile128(sm, SB_HI, Bh, Dc, k0, tid);
        load_tile128(sm, SB_LO, Bl, Dc, k0, tid);
        __syncthreads();
        mma_chunk_128x128(smb, wm, wn, lane, acc);
        __syncthreads();
    }

    // Epilogue: stage per 64-col half through smem, add bias, scatter.
    float* sf = (float*)sm;
    int mBase = mT * 128, b = mBase >> 10, l0 = mBase & 1023;
    for (int half = 0; half < 2; half++) {
        if (wn == half) {
            #pragma unroll
            for (int mi = 0; mi < 2; mi++)
                #pragma unroll
                for (int ni = 0; ni < 8; ni++) {
                    int r0 = wm*32 + mi*16 + (lane >> 2);
                    int c0 = ni*8 + (lane & 3)*2;
                    sf[r0*72 + c0]     = acc[mi][ni][0];
                    sf[r0*72 + c0 + 1] = acc[mi][ni][1];
                    sf[(r0+8)*72 + c0]     = acc[mi][ni][2];
                    sf[(r0+8)*72 + c0 + 1] = acc[mi][ni][3];
                }
        }
        __syncthreads();
        int head = nT*2 + half;
        int bh = b*16 + head;
        if (w == 2) {  // V: transpose -> vt[bh][hd][l]
            for (int idx = tid; idx < 64*128; idx += 256) {
                int hd = idx >> 7, ll = idx & 127;
                float x = sf[ll*72 + hd] + __ldg(&bias[head*64 + hd]);
                __nv_bfloat16 h = __float2bfloat16(x);
                size_t o = ((size_t)bh*64 + hd)*1024 + l0 + ll;
                g_vt_hi[o] = h;
                g_vt_lo[o] = __float2bfloat16(x - __bfloat162float(h));
            }
        } else {
            __nv_bfloat16* dhi = (w == 0 || w == 3) ? g_qq2_hi : g_kk2_hi;
            __nv_bfloat16* dlo = (w == 0 || w == 3) ? g_qq2_lo : g_kk2_lo;
            int co = (w >= 3) ? 64 : 0;
            for (int idx = tid; idx < 128*32; idx += 256) {
                int r = idx >> 5, c2 = (idx & 31)*2;
                float x0 = sf[r*72 + c2]     + __ldg(&bias[head*64 + c2]);
                float x1 = sf[r*72 + c2 + 1] + __ldg(&bias[head*64 + c2 + 1]);
                __nv_bfloat16 h0 = __float2bfloat16(x0), h1 = __float2bfloat16(x1);
                __nv_bfloat162 hp; hp.x = h0; hp.y = h1;
                __nv_bfloat162 lp;
                lp.x = __float2bfloat16(x0 - __bfloat162float(h0));
                lp.y = __float2bfloat16(x1 - __bfloat162float(h1));
                size_t o = ((size_t)bh*1024 + l0 + r)*128 + co + c2;
                *(__nv_bfloat162*)&dhi[o] = hp;
                *(__nv_bfloat162*)&dlo[o] = lp;
            }
        }
        __syncthreads();
    }
}

// ------------------------- scores GEMM ---------------------------------------
// grid (8, 8, 128), block 256. S = (QQ2 · KK2^T)*scale + mask, K=128.
__global__ __launch_bounds__(256) void scores_gemm(const float* __restrict__ mask)
{
    __shared__ __align__(16) char sm[40960];
    uint32_t smb = smem_u32(sm);
    int nT = blockIdx.x, mT = blockIdx.y, bh = blockIdx.z;
    const __nv_bfloat16* Ah = g_qq2_hi + ((size_t)bh*1024 + mT*128) * 128;
    const __nv_bfloat16* Al = g_qq2_lo + ((size_t)bh*1024 + mT*128) * 128;
    const __nv_bfloat16* Bh = g_kk2_hi + ((size_t)bh*1024 + nT*128) * 128;
    const __nv_bfloat16* Bl = g_kk2_lo + ((size_t)bh*1024 + nT*128) * 128;

    int tid = threadIdx.x, lane = tid & 31, wid = tid >> 5;
    int wm = wid & 3, wn = wid >> 2;

    float acc[2][8][4];
    #pragma unroll
    for (int a = 0; a < 2; a++)
        #pragma unroll
        for (int b = 0; b < 8; b++)
            #pragma unroll
            for (int c = 0; c < 4; c++) acc[a][b][c] = 0.f;

    for (int k0 = 0; k0 < 128; k0 += 32) {
        load_tile128(sm, SA_HI, Ah, 128, k0, tid);
        load_tile128(sm, SA_LO, Al, 128, k0, tid);
        load_tile128(sm, SB_HI, Bh, 128, k0, tid);
        load_tile128(sm, SB_LO, Bl, 128, k0, tid);
        __syncthreads();
        mma_chunk_128x128(smb, wm, wn, lane, acc);
        __syncthreads();
    }

    int b = bh >> 4;
    size_t Srow = (size_t)bh*1024 + mT*128;
    #pragma unroll
    for (int mi = 0; mi < 2; mi++) {
        int r0 = wm*32 + mi*16 + (lane >> 2);
        #pragma unroll
        for (int ni = 0; ni < 8; ni++) {
            int c = nT*128 + wn*64 + ni*8 + (lane & 3)*2;
            float mk0 = __ldg(&mask[(size_t)b*1024 + c]);
            float mk1 = __ldg(&mask[(size_t)b*1024 + c + 1]);
            float2 v0 = make_float2(acc[mi][ni][0]*0.125f + mk0, acc[mi][ni][1]*0.125f + mk1);
            float2 v1 = make_float2(acc[mi][ni][2]*0.125f + mk0, acc[mi][ni][3]*0.125f + mk1);
            *(float2*)&g_scores[(Srow + r0)*1024 + c]     = v0;
            *(float2*)&g_scores[(Srow + r0 + 8)*1024 + c] = v1;
        }
    }
}

// ------------------------- softmax -> bf16 hi/lo probs -----------------------
__global__ __launch_bounds__(256) void softmax_split()
{
    size_t row = blockIdx.x;
    const float* p = g_scores + row * 1024;
    int tid = threadIdx.x, lane = tid & 31, wid = tid >> 5;
    __shared__ float red[8];

    float4 v = *(const float4*)&p[tid * 4];
    float m = fmaxf(fmaxf(v.x, v.y), fmaxf(v.z, v.w));
    #pragma unroll
    for (int o = 16; o > 0; o >>= 1) m = fmaxf(m, __shfl_xor_sync(0xffffffffu, m, o));
    if (lane == 0) red[wid] = m;
    __syncthreads();
    if (tid == 0) {
        float mm = red[0];
        #pragma unroll
        for (int i = 1; i < 8; i++) mm = fmaxf(mm, red[i]);
        red[0] = mm;
    }
    __syncthreads();
    m = red[0];
    __syncthreads();

    float e[4];
    e[0] = expf(v.x - m); e[1] = expf(v.y - m); e[2] = expf(v.z - m); e[3] = expf(v.w - m);
    float s = e[0] + e[1] + e[2] + e[3];
    #pragma unroll
    for (int o = 16; o > 0; o >>= 1) s += __shfl_xor_sync(0xffffffffu, s, o);
    if (lane == 0) red[wid] = s;
    __syncthreads();
    if (tid == 0) {
        float ss = red[0];
        #pragma unroll
        for (int i = 1; i < 8; i++) ss += red[i];
        red[0] = ss;
    }
    __syncthreads();
    float inv = 1.f / red[0];

    size_t o = row * 1024 + tid * 4;
    #pragma unroll
    for (int j = 0; j < 4; j += 2) {
        float x0 = e[j] * inv, x1 = e[j + 1] * inv;
        __nv_bfloat16 h0 = __float2bfloat16(x0), h1 = __float2bfloat16(x1);
        __nv_bfloat162 hp; hp.x = h0; hp.y = h1;
        __nv_bfloat162 lp;
        lp.x = __float2bfloat16(x0 - __bfloat162float(h0));
        lp.y = __float2bfloat16(x1 - __bfloat162float(h1));
        *(__nv_bfloat162*)&g_p_hi[o + j] = hp;
        *(__nv_bfloat162*)&g_p_lo[o + j] = lp;
    }
}

// ------------------------- PV GEMM -------------------------------------------
// grid (8, 128), block 256. Tile 128(M) x 64(N), K=1024. Direct write to out.
#define PB_HI 20480
#define PB_LO 25600
__global__ __launch_bounds__(256) void pv_gemm(float* __restrict__ out)
{
    __shared__ __align__(16) char sm[30720];
    uint32_t smb = smem_u32(sm);
    int mT = blockIdx.x, bh = blockIdx.y;
    const __nv_bfloat16* Ah = g_p_hi + ((size_t)bh*1024 + mT*128) * 1024;
    const __nv_bfloat16* Al = g_p_lo + ((size_t)bh*1024 + mT*128) * 1024;
    const __nv_bfloat16* Bh = g_vt_hi + (size_t)bh*64*1024;
    const __nv_bfloat16* Bl = g_vt_lo + (size_t)bh*64*1024;

    int tid = threadIdx.x, lane = tid & 31, wm = tid >> 5;  // 8 warps over M
    int arow = (lane & 7) + ((lane >> 3) & 1) * 8;
    int acol = (lane >> 4) * 8;

    float acc[8][4];
    #pragma unroll
    for (int b = 0; b < 8; b++)
        #pragma unroll
        for (int c = 0; c < 4; c++) acc[b][c] = 0.f;

    for (int k0 = 0; k0 < 1024; k0 += 32) {
        load_tile128(sm, SA_HI, Ah, 1024, k0, tid);
        load_tile128(sm, SA_LO, Al, 1024, k0, tid);
        {   // B: 64 rows
            int r = tid >> 2, c8 = (tid & 3) << 3;
            *(uint4*)(sm + PB_HI + (r*TSTR + c8)*2) = *(const uint4*)(Bh + (size_t)r*1024 + k0 + c8);
            *(uint4*)(sm + PB_LO + (r*TSTR + c8)*2) = *(const uint4*)(Bl + (size_t)r*1024 + k0 + c8);
        }
        __syncthreads();
        #pragma unroll
        for (int pass = 0; pass < 3; pass++) {
            uint32_t aB = smb + ((pass == 1) ? SA_LO : SA_HI);
            uint32_t bB = smb + ((pass == 2) ? PB_LO : PB_HI);
            #pragma unroll
            for (int ks = 0; ks < 2; ks++) {
                uint32_t af[4];
                ldsm4(af, aB + (uint32_t)((wm*16 + arow)*TSTR + ks*16 + acol)*2);
                #pragma unroll
                for (int nb = 0; nb < 4; nb++) {
                    uint32_t bt[4];
                    ldsm4(bt, bB + (uint32_t)((nb*16 + arow)*TSTR + ks*16 + acol)*2);
                    mma16816(acc[nb*2],     af, bt[0], bt[2]);
                    mma16816(acc[nb*2 + 1], af, bt[1], bt[3]);
                }
            }
        }
        __syncthreads();
    }

    int b = bh >> 4, h = bh & 15;
    int r0 = mT*128 + wm*16 + (lane >> 2);
    #pragma unroll
    for (int ni = 0; ni < 8; ni++) {
        int c = h*64 + ni*8 + (lane & 3)*2;
        *(float2*)&out[((size_t)b*1024 + r0)*1024 + c]     = make_float2(acc[ni][0], acc[ni][1]);
        *(float2*)&out[((size_t)b*1024 + r0 + 8)*1024 + c] = make_float2(acc[ni][2], acc[ni][3]);
    }
}

// ------------------------- launch --------------------------------------------
extern "C" void kernel_launch(void* const* d_in, const int* in_sizes, int n_in,
                              void* d_out, int out_size)
{
    (void)in_sizes; (void)n_in; (void)out_size;
    const float* hidden = (const float*)d_in[0];
    const float* mask   = (const float*)d_in[1];
    const float* source = (const float*)d_in[2];
    const float* bq  = (const float*)d_in[4];
    const float* bk  = (const float*)d_in[6];
    const float* bv  = (const float*)d_in[8];
    const float* bq2 = (const float*)d_in[10];
    const float* bk2 = (const float*)d_in[12];
    float* out = (float*)d_out;

    split_acts<<<8192, 256>>>(hidden, 0);
    split_acts<<<8192, 256>>>(source, 1);
    split_wt<<<dim3(32, 32, 5), 256>>>((const float*)d_in[3], (const float*)d_in[5],
                                       (const float*)d_in[7], (const float*)d_in[9],
                                       (const float*)d_in[11]);
    proj_gemm<<<dim3(8, 64, 5), 256>>>(bq, bk, bv, bq2, bk2);
    scores_gemm<<<dim3(8, 8, 128), 256>>>(mask);
    softmax_split<<<131072, 256>>>();
    pv_gemm<<<dim3(8, 128), 256>>>(out);
}

// round 8
// speedup vs baseline: 2.7450x; 1.0498x over previous
#include <cuda_runtime.h>
#include <cuda_bf16.h>
#include <stdint.h>
#include <math.h>

#define Dc 1024

// ------------------------- scratch (__device__ globals) ---------------------
__device__ __align__(128) __nv_bfloat16 g_hid_hi[8192*1024];
__device__ __align__(128) __nv_bfloat16 g_hid_lo[8192*1024];
__device__ __align__(128) __nv_bfloat16 g_src_hi[8192*1024];
__device__ __align__(128) __nv_bfloat16 g_src_lo[8192*1024];
__device__ __align__(128) __nv_bfloat16 g_wt_hi[5*1024*1024];
__device__ __align__(128) __nv_bfloat16 g_wt_lo[5*1024*1024];
__device__ __align__(128) __nv_bfloat16 g_qq2_hi[(size_t)128*1024*128];
__device__ __align__(128) __nv_bfloat16 g_qq2_lo[(size_t)128*1024*128];
__device__ __align__(128) __nv_bfloat16 g_kk2_hi[(size_t)128*1024*128];
__device__ __align__(128) __nv_bfloat16 g_kk2_lo[(size_t)128*1024*128];
__device__ __align__(128) __nv_bfloat16 g_vt_hi[(size_t)128*64*1024];
__device__ __align__(128) __nv_bfloat16 g_vt_lo[(size_t)128*64*1024];
__device__ __align__(128) float          g_scores[(size_t)134217728];
__device__ __align__(128) __nv_bfloat16 g_p_hi[(size_t)134217728];
__device__ __align__(128) __nv_bfloat16 g_p_lo[(size_t)134217728];

// ------------------------- warp-MMA helpers ----------------------------------
__device__ __forceinline__ uint32_t smem_u32(const void* p) {
    uint32_t a;
    asm("{ .reg .u64 t; cvta.to.shared.u64 t, %1; cvt.u32.u64 %0, t; }" : "=r"(a) : "l"(p));
    return a;
}
__device__ __forceinline__ void ldsm4(uint32_t* r, uint32_t addr) {
    asm volatile("ldmatrix.sync.aligned.m8n8.x4.shared.b16 {%0,%1,%2,%3}, [%4];"
        : "=r"(r[0]), "=r"(r[1]), "=r"(r[2]), "=r"(r[3]) : "r"(addr));
}
__device__ __forceinline__ void mma16816(float* c, const uint32_t* a, uint32_t b0, uint32_t b1) {
    asm volatile(
        "mma.sync.aligned.m16n8k16.row.col.f32.bf16.bf16.f32 "
        "{%0,%1,%2,%3}, {%4,%5,%6,%7}, {%8,%9}, {%0,%1,%2,%3};"
        : "+f"(c[0]), "+f"(c[1]), "+f"(c[2]), "+f"(c[3])
        : "r"(a[0]), "r"(a[1]), "r"(a[2]), "r"(a[3]), "r"(b0), "r"(b1));
}

// smem tile layout: rows of 40 bf16 (32 data + 8 pad) = 80B stride
#define TSTR 40
#define SA_HI 0
#define SA_LO 10240
#define SB_HI 20480
#define SB_LO 30720

__device__ __forceinline__ void load_tile128(char* sm, int off, const __nv_bfloat16* src,
                                             int ld, int k0, int tid) {
    #pragma unroll
    for (int i = 0; i < 2; i++) {
        int idx = tid + i * 256;
        int r = idx >> 2, c8 = (idx & 3) << 3;
        *(uint4*)(sm + off + (r * TSTR + c8) * 2) = *(const uint4*)(src + (size_t)r * ld + k0 + c8);
    }
}
// register prefetch (128-row tile = 2 uint4/thread @256 threads)
__device__ __forceinline__ void pf_load(uint4* pf, const __nv_bfloat16* src, int ld, int k0, int tid) {
    #pragma unroll
    for (int i = 0; i < 2; i++) {
        int idx = tid + i * 256;
        int r = idx >> 2, c8 = (idx & 3) << 3;
        pf[i] = *(const uint4*)(src + (size_t)r * ld + k0 + c8);
    }
}
__device__ __forceinline__ void pf_store(const uint4* pf, char* sm, int off, int tid) {
    #pragma unroll
    for (int i = 0; i < 2; i++) {
        int idx = tid + i * 256;
        int r = idx >> 2, c8 = (idx & 3) << 3;
        *(uint4*)(sm + off + (r * TSTR + c8) * 2) = pf[i];
    }
}

// 3-pass (AhBh + AlBh + AhBl) 128x128 MMA over one BK=32 chunk already in smem.
__device__ __forceinline__ void mma_chunk_128x128(uint32_t smb, int wm, int wn, int lane,
                                                  float acc[2][8][4]) {
    int arow = (lane & 7) + ((lane >> 3) & 1) * 8;
    int acol = (lane >> 4) * 8;
    #pragma unroll
    for (int pass = 0; pass < 3; pass++) {
        uint32_t aB = smb + ((pass == 1) ? SA_LO : SA_HI);
        uint32_t bB = smb + ((pass == 2) ? SB_LO : SB_HI);
        #pragma unroll
        for (int ks = 0; ks < 2; ks++) {
            uint32_t af[2][4];
            #pragma unroll
            for (int mi = 0; mi < 2; mi++)
                ldsm4(af[mi], aB + (uint32_t)((wm*32 + mi*16 + arow) * TSTR + ks*16 + acol) * 2);
            #pragma unroll
            for (int nb = 0; nb < 4; nb++) {
                uint32_t bt[4];
                ldsm4(bt, bB + (uint32_t)((wn*64 + nb*16 + arow) * TSTR + ks*16 + acol) * 2);
                #pragma unroll
                for (int mi = 0; mi < 2; mi++) {
                    mma16816(acc[mi][nb*2],     af[mi], bt[0], bt[2]);
                    mma16816(acc[mi][nb*2 + 1], af[mi], bt[1], bt[3]);
                }
            }
        }
    }
}

// ------------------------- conversion kernels --------------------------------
__global__ __launch_bounds__(256) void split_acts(const float* __restrict__ in, int which)
{
    __nv_bfloat16* hi = which ? g_src_hi : g_hid_hi;
    __nv_bfloat16* lo = which ? g_src_lo : g_hid_lo;
    size_t i = ((size_t)blockIdx.x * 256 + threadIdx.x) * 4;
    float4 v = *(const float4*)(in + i);
    float x[4] = {v.x, v.y, v.z, v.w};
    #pragma unroll
    for (int j = 0; j < 4; j++) {
        __nv_bfloat16 h = __float2bfloat16(x[j]);
        hi[i + j] = h;
        lo[i + j] = __float2bfloat16(x[j] - __bfloat162float(h));
    }
}

__global__ __launch_bounds__(256) void split_wt(
    const float* __restrict__ Wq, const float* __restrict__ Wk, const float* __restrict__ Wv,
    const float* __restrict__ Wq2, const float* __restrict__ Wk2)
{
    __shared__ float t[32][33];
    int w = blockIdx.z;
    const float* W = (w==0)?Wq:(w==1)?Wk:(w==2)?Wv:(w==3)?Wq2:Wk2;
    int tx = threadIdx.x & 31, ty = threadIdx.x >> 5;
    int n0 = blockIdx.x * 32, k0 = blockIdx.y * 32;
    #pragma unroll
    for (int j = 0; j < 32; j += 8)
        t[ty + j][tx] = W[(size_t)(k0 + ty + j) * Dc + n0 + tx];
    __syncthreads();
    size_t woff = (size_t)w * Dc * Dc;
    #pragma unroll
    for (int j = 0; j < 32; j += 8) {
        float x = t[tx][ty + j];
        __nv_bfloat16 h = __float2bfloat16(x);
        size_t o = woff + (size_t)(n0 + ty + j) * Dc + k0 + tx;
        g_wt_hi[o] = h;
        g_wt_lo[o] = __float2bfloat16(x - __bfloat162float(h));
    }
}

// ------------------------- projection GEMM -----------------------------------
// grid (8, 64, 5), block 256. Tile 128(M) x 128(N), K=1024. Reg-prefetch pipeline.
__global__ __launch_bounds__(256) void proj_gemm(
    const float* __restrict__ bq, const float* __restrict__ bk, const float* __restrict__ bv,
    const float* __restrict__ bq2, const float* __restrict__ bk2)
{
    __shared__ __align__(16) char sm[40960];
    uint32_t smb = smem_u32(sm);
    int w = blockIdx.z, nT = blockIdx.x, mT = blockIdx.y;
    const __nv_bfloat16* Ah = ((w == 4) ? g_src_hi : g_hid_hi) + (size_t)mT * 128 * Dc;
    const __nv_bfloat16* Al = ((w == 4) ? g_src_lo : g_hid_lo) + (size_t)mT * 128 * Dc;
    size_t woff = (size_t)w * Dc * Dc + (size_t)nT * 128 * Dc;
    const __nv_bfloat16* Bh = g_wt_hi + woff;
    const __nv_bfloat16* Bl = g_wt_lo + woff;
    const float* bias = (w==0)?bq:(w==1)?bk:(w==2)?bv:(w==3)?bq2:bk2;

    int tid = threadIdx.x, lane = tid & 31, wid = tid >> 5;
    int wm = wid & 3, wn = wid >> 2;

    float acc[2][8][4];
    #pragma unroll
    for (int a = 0; a < 2; a++)
        #pragma unroll
        for (int b = 0; b < 8; b++)
            #pragma unroll
            for (int c = 0; c < 4; c++) acc[a][b][c] = 0.f;

    load_tile128(sm, SA_HI, Ah, Dc, 0, tid);
    load_tile128(sm, SA_LO, Al, Dc, 0, tid);
    load_tile128(sm, SB_HI, Bh, Dc, 0, tid);
    load_tile128(sm, SB_LO, Bl, Dc, 0, tid);
    __syncthreads();

    for (int c = 0; c < 32; c++) {
        uint4 pAh[2], pAl[2], pBh[2], pBl[2];
        if (c < 31) {
            int kn = (c + 1) * 32;
            pf_load(pAh, Ah, Dc, kn, tid);
            pf_load(pAl, Al, Dc, kn, tid);
            pf_load(pBh, Bh, Dc, kn, tid);
            pf_load(pBl, Bl, Dc, kn, tid);
        }
        mma_chunk_128x128(smb, wm, wn, lane, acc);
        __syncthreads();
        if (c < 31) {
            pf_store(pAh, sm, SA_HI, tid);
            pf_store(pAl, sm, SA_LO, tid);
            pf_store(pBh, sm, SB_HI, tid);
            pf_store(pBl, sm, SB_LO, tid);
            __syncthreads();
        }
    }

    // Epilogue: stage per 64-col half through smem, add bias, scatter.
    float* sf = (float*)sm;
    int mBase = mT * 128, b = mBase >> 10, l0 = mBase & 1023;
    for (int half = 0; half < 2; half++) {
        if (wn == half) {
            #pragma unroll
            for (int mi = 0; mi < 2; mi++)
                #pragma unroll
                for (int ni = 0; ni < 8; ni++) {
                    int r0 = wm*32 + mi*16 + (lane >> 2);
                    int c0 = ni*8 + (lane & 3)*2;
                    sf[r0*72 + c0]     = acc[mi][ni][0];
                    sf[r0*72 + c0 + 1] = acc[mi][ni][1];
                    sf[(r0+8)*72 + c0]     = acc[mi][ni][2];
                    sf[(r0+8)*72 + c0 + 1] = acc[mi][ni][3];
                }
        }
        __syncthreads();
        int head = nT*2 + half;
        int bh = b*16 + head;
        if (w == 2) {  // V: transpose -> vt[bh][hd][l]
            for (int idx = tid; idx < 64*128; idx += 256) {
                int hd = idx >> 7, ll = idx & 127;
                float x = sf[ll*72 + hd] + __ldg(&bias[head*64 + hd]);
                __nv_bfloat16 h = __float2bfloat16(x);
                size_t o = ((size_t)bh*64 + hd)*1024 + l0 + ll;
                g_vt_hi[o] = h;
                g_vt_lo[o] = __float2bfloat16(x - __bfloat162float(h));
            }
        } else {
            __nv_bfloat16* dhi = (w == 0 || w == 3) ? g_qq2_hi : g_kk2_hi;
            __nv_bfloat16* dlo = (w == 0 || w == 3) ? g_qq2_lo : g_kk2_lo;
            int co = (w >= 3) ? 64 : 0;
            for (int idx = tid; idx < 128*32; idx += 256) {
                int r = idx >> 5, c2 = (idx & 31)*2;
                float x0 = sf[r*72 + c2]     + __ldg(&bias[head*64 + c2]);
                float x1 = sf[r*72 + c2 + 1] + __ldg(&bias[head*64 + c2 + 1]);
                __nv_bfloat16 h0 = __float2bfloat16(x0), h1 = __float2bfloat16(x1);
                __nv_bfloat162 hp; hp.x = h0; hp.y = h1;
                __nv_bfloat162 lp;
                lp.x = __float2bfloat16(x0 - __bfloat162float(h0));
                lp.y = __float2bfloat16(x1 - __bfloat162float(h1));
                size_t o = ((size_t)bh*1024 + l0 + r)*128 + co + c2;
                *(__nv_bfloat162*)&dhi[o] = hp;
                *(__nv_bfloat162*)&dlo[o] = lp;
            }
        }
        __syncthreads();
    }
}

// ------------------------- scores GEMM ---------------------------------------
// grid (8, 8, 128), block 256. S = (QQ2 · KK2^T)*scale + mask, K=128.
__global__ __launch_bounds__(256) void scores_gemm(const float* __restrict__ mask)
{
    __shared__ __align__(16) char sm[40960];
    uint32_t smb = smem_u32(sm);
    int nT = blockIdx.x, mT = blockIdx.y, bh = blockIdx.z;
    const __nv_bfloat16* Ah = g_qq2_hi + ((size_t)bh*1024 + mT*128) * 128;
    const __nv_bfloat16* Al = g_qq2_lo + ((size_t)bh*1024 + mT*128) * 128;
    const __nv_bfloat16* Bh = g_kk2_hi + ((size_t)bh*1024 + nT*128) * 128;
    const __nv_bfloat16* Bl = g_kk2_lo + ((size_t)bh*1024 + nT*128) * 128;

    int tid = threadIdx.x, lane = tid & 31, wid = tid >> 5;
    int wm = wid & 3, wn = wid >> 2;

    float acc[2][8][4];
    #pragma unroll
    for (int a = 0; a < 2; a++)
        #pragma unroll
        for (int b = 0; b < 8; b++)
            #pragma unroll
            for (int c = 0; c < 4; c++) acc[a][b][c] = 0.f;

    load_tile128(sm, SA_HI, Ah, 128, 0, tid);
    load_tile128(sm, SA_LO, Al, 128, 0, tid);
    load_tile128(sm, SB_HI, Bh, 128, 0, tid);
    load_tile128(sm, SB_LO, Bl, 128, 0, tid);
    __syncthreads();

    #pragma unroll
    for (int c = 0; c < 4; c++) {
        uint4 pAh[2], pAl[2], pBh[2], pBl[2];
        if (c < 3) {
            int kn = (c + 1) * 32;
            pf_load(pAh, Ah, 128, kn, tid);
            pf_load(pAl, Al, 128, kn, tid);
            pf_load(pBh, Bh, 128, kn, tid);
            pf_load(pBl, Bl, 128, kn, tid);
        }
        mma_chunk_128x128(smb, wm, wn, lane, acc);
        __syncthreads();
        if (c < 3) {
            pf_store(pAh, sm, SA_HI, tid);
            pf_store(pAl, sm, SA_LO, tid);
            pf_store(pBh, sm, SB_HI, tid);
            pf_store(pBl, sm, SB_LO, tid);
            __syncthreads();
        }
    }

    int b = bh >> 4;
    size_t Srow = (size_t)bh*1024 + mT*128;
    #pragma unroll
    for (int mi = 0; mi < 2; mi++) {
        int r0 = wm*32 + mi*16 + (lane >> 2);
        #pragma unroll
        for (int ni = 0; ni < 8; ni++) {
            int c = nT*128 + wn*64 + ni*8 + (lane & 3)*2;
            float mk0 = __ldg(&mask[(size_t)b*1024 + c]);
            float mk1 = __ldg(&mask[(size_t)b*1024 + c + 1]);
            float2 v0 = make_float2(acc[mi][ni][0]*0.125f + mk0, acc[mi][ni][1]*0.125f + mk1);
            float2 v1 = make_float2(acc[mi][ni][2]*0.125f + mk0, acc[mi][ni][3]*0.125f + mk1);
            *(float2*)&g_scores[(Srow + r0)*1024 + c]     = v0;
            *(float2*)&g_scores[(Srow + r0 + 8)*1024 + c] = v1;
        }
    }
}

// ------------------------- softmax -> bf16 hi/lo probs -----------------------
__global__ __launch_bounds__(256) void softmax_split()
{
    size_t row = blockIdx.x;
    const float* p = g_scores + row * 1024;
    int tid = threadIdx.x, lane = tid & 31, wid = tid >> 5;
    __shared__ float red[8];

    float4 v = *(const float4*)&p[tid * 4];
    float m = fmaxf(fmaxf(v.x, v.y), fmaxf(v.z, v.w));
    #pragma unroll
    for (int o = 16; o > 0; o >>= 1) m = fmaxf(m, __shfl_xor_sync(0xffffffffu, m, o));
    if (lane == 0) red[wid] = m;
    __syncthreads();
    if (tid == 0) {
        float mm = red[0];
        #pragma unroll
        for (int i = 1; i < 8; i++) mm = fmaxf(mm, red[i]);
        red[0] = mm;
    }
    __syncthreads();
    m = red[0];
    __syncthreads();

    float e[4];
    e[0] = expf(v.x - m); e[1] = expf(v.y - m); e[2] = expf(v.z - m); e[3] = expf(v.w - m);
    float s = e[0] + e[1] + e[2] + e[3];
    #pragma unroll
    for (int o = 16; o > 0; o >>= 1) s += __shfl_xor_sync(0xffffffffu, s, o);
    if (lane == 0) red[wid] = s;
    __syncthreads();
    if (tid == 0) {
        float ss = red[0];
        #pragma unroll
        for (int i = 1; i < 8; i++) ss += red[i];
        red[0] = ss;
    }
    __syncthreads();
    float inv = 1.f / red[0];

    size_t o = row * 1024 + tid * 4;
    #pragma unroll
    for (int j = 0; j < 4; j += 2) {
        float x0 = e[j] * inv, x1 = e[j + 1] * inv;
        __nv_bfloat16 h0 = __float2bfloat16(x0), h1 = __float2bfloat16(x1);
        __nv_bfloat162 hp; hp.x = h0; hp.y = h1;
        __nv_bfloat162 lp;
        lp.x = __float2bfloat16(x0 - __bfloat162float(h0));
        lp.y = __float2bfloat16(x1 - __bfloat162float(h1));
        *(__nv_bfloat162*)&g_p_hi[o + j] = hp;
        *(__nv_bfloat162*)&g_p_lo[o + j] = lp;
    }
}

// ------------------------- PV GEMM -------------------------------------------
// grid (8, 128), block 256. Tile 128(M) x 64(N), K=1024. Reg-prefetch pipeline.
#define PB_HI 20480
#define PB_LO 25600
__global__ __launch_bounds__(256) void pv_gemm(float* __restrict__ out)
{
    __shared__ __align__(16) char sm[30720];
    uint32_t smb = smem_u32(sm);
    int mT = blockIdx.x, bh = blockIdx.y;
    const __nv_bfloat16* Ah = g_p_hi + ((size_t)bh*1024 + mT*128) * 1024;
    const __nv_bfloat16* Al = g_p_lo + ((size_t)bh*1024 + mT*128) * 1024;
    const __nv_bfloat16* Bh = g_vt_hi + (size_t)bh*64*1024;
    const __nv_bfloat16* Bl = g_vt_lo + (size_t)bh*64*1024;

    int tid = threadIdx.x, lane = tid & 31, wm = tid >> 5;  // 8 warps over M
    int arow = (lane & 7) + ((lane >> 3) & 1) * 8;
    int acol = (lane >> 4) * 8;
    int br = tid >> 2, bc8 = (tid & 3) << 3;   // B tile: 64 rows, 1 uint4/thread

    float acc[8][4];
    #pragma unroll
    for (int b = 0; b < 8; b++)
        #pragma unroll
        for (int c = 0; c < 4; c++) acc[b][c] = 0.f;

    load_tile128(sm, SA_HI, Ah, 1024, 0, tid);
    load_tile128(sm, SA_LO, Al, 1024, 0, tid);
    *(uint4*)(sm + PB_HI + (br*TSTR + bc8)*2) = *(const uint4*)(Bh + (size_t)br*1024 + bc8);
    *(uint4*)(sm + PB_LO + (br*TSTR + bc8)*2) = *(const uint4*)(Bl + (size_t)br*1024 + bc8);
    __syncthreads();

    for (int k = 0; k < 32; k++) {
        uint4 pAh[2], pAl[2], pBh, pBl;
        if (k < 31) {
            int kn = (k + 1) * 32;
            pf_load(pAh, Ah, 1024, kn, tid);
            pf_load(pAl, Al, 1024, kn, tid);
            pBh = *(const uint4*)(Bh + (size_t)br*1024 + kn + bc8);
            pBl = *(const uint4*)(Bl + (size_t)br*1024 + kn + bc8);
        }
        #pragma unroll
        for (int pass = 0; pass < 3; pass++) {
            uint32_t aB = smb + ((pass == 1) ? SA_LO : SA_HI);
            uint32_t bB = smb + ((pass == 2) ? PB_LO : PB_HI);
            #pragma unroll
            for (int ks = 0; ks < 2; ks++) {
                uint32_t af[4];
                ldsm4(af, aB + (uint32_t)((wm*16 + arow)*TSTR + ks*16 + acol)*2);
                #pragma unroll
                for (int nb = 0; nb < 4; nb++) {
                    uint32_t bt[4];
                    ldsm4(bt, bB + (uint32_t)((nb*16 + arow)*TSTR + ks*16 + acol)*2);
                    mma16816(acc[nb*2],     af, bt[0], bt[2]);
                    mma16816(acc[nb*2 + 1], af, bt[1], bt[3]);
                }
            }
        }
        __syncthreads();
        if (k < 31) {
            pf_store(pAh, sm, SA_HI, tid);
            pf_store(pAl, sm, SA_LO, tid);
            *(uint4*)(sm + PB_HI + (br*TSTR + bc8)*2) = pBh;
            *(uint4*)(sm + PB_LO + (br*TSTR + bc8)*2) = pBl;
            __syncthreads();
        }
    }

    int b = bh >> 4, h = bh & 15;
    int r0 = mT*128 + wm*16 + (lane >> 2);
    #pragma unroll
    for (int ni = 0; ni < 8; ni++) {
        int c = h*64 + ni*8 + (lane & 3)*2;
        *(float2*)&out[((size_t)b*1024 + r0)*1024 + c]     = make_float2(acc[ni][0], acc[ni][1]);
        *(float2*)&out[((size_t)b*1024 + r0 + 8)*1024 + c] = make_float2(acc[ni][2], acc[ni][3]);
    }
}

// ------------------------- launch --------------------------------------------
extern "C" void kernel_launch(void* const* d_in, const int* in_sizes, int n_in,
                              void* d_out, int out_size)
{
    (void)in_sizes; (void)n_in; (void)out_size;
    const float* hidden = (const float*)d_in[0];
    const float* mask   = (const float*)d_in[1];
    const float* source = (const float*)d_in[2];
    const float* bq  = (const float*)d_in[4];
    const float* bk  = (const float*)d_in[6];
    const float* bv  = (const float*)d_in[8];
    const float* bq2 = (const float*)d_in[10];
    const float* bk2 = (const float*)d_in[12];
    float* out = (float*)d_out;

    split_acts<<<8192, 256>>>(hidden, 0);
    split_acts<<<8192, 256>>>(source, 1);
    split_wt<<<dim3(32, 32, 5), 256>>>((const float*)d_in[3], (const float*)d_in[5],
                                       (const float*)d_in[7], (const float*)d_in[9],
                                       (const float*)d_in[11]);
    proj_gemm<<<dim3(8, 64, 5), 256>>>(bq, bk, bv, bq2, bk2);
    scores_gemm<<<dim3(8, 8, 128), 256>>>(mask);
    softmax_split<<<131072, 256>>>();
    pv_gemm<<<dim3(8, 128), 256>>>(out);
}

// round 9
// speedup vs baseline: 2.7776x; 1.0119x over previous
#include <cuda_runtime.h>
#include <cuda_bf16.h>
#include <stdint.h>
#include <math.h>

#define Dc 1024

// ------------------------- scratch (__device__ globals) ---------------------
__device__ __align__(128) __nv_bfloat16 g_hid_hi[8192*1024];
__device__ __align__(128) __nv_bfloat16 g_hid_lo[8192*1024];
__device__ __align__(128) __nv_bfloat16 g_src_hi[8192*1024];
__device__ __align__(128) __nv_bfloat16 g_src_lo[8192*1024];
__device__ __align__(128) __nv_bfloat16 g_wt_hi[5*1024*1024];
__device__ __align__(128) __nv_bfloat16 g_wt_lo[5*1024*1024];
__device__ __align__(128) __nv_bfloat16 g_qq2_hi[(size_t)128*1024*128];
__device__ __align__(128) __nv_bfloat16 g_qq2_lo[(size_t)128*1024*128];
__device__ __align__(128) __nv_bfloat16 g_kk2_hi[(size_t)128*1024*128];
__device__ __align__(128) __nv_bfloat16 g_kk2_lo[(size_t)128*1024*128];
__device__ __align__(128) __nv_bfloat16 g_vt_hi[(size_t)128*64*1024];
__device__ __align__(128) __nv_bfloat16 g_vt_lo[(size_t)128*64*1024];
__device__ __align__(128) float          g_scores[(size_t)134217728];
__device__ __align__(128) __nv_bfloat16 g_p_hi[(size_t)134217728];
__device__ __align__(128) __nv_bfloat16 g_p_lo[(size_t)134217728];

// ------------------------- warp-MMA / async helpers --------------------------
__device__ __forceinline__ uint32_t smem_u32(const void* p) {
    uint32_t a;
    asm("{ .reg .u64 t; cvta.to.shared.u64 t, %1; cvt.u32.u64 %0, t; }" : "=r"(a) : "l"(p));
    return a;
}
__device__ __forceinline__ void ldsm4(uint32_t* r, uint32_t addr) {
    asm volatile("ldmatrix.sync.aligned.m8n8.x4.shared.b16 {%0,%1,%2,%3}, [%4];"
        : "=r"(r[0]), "=r"(r[1]), "=r"(r[2]), "=r"(r[3]) : "r"(addr));
}
__device__ __forceinline__ void mma16816(float* c, const uint32_t* a, uint32_t b0, uint32_t b1) {
    asm volatile(
        "mma.sync.aligned.m16n8k16.row.col.f32.bf16.bf16.f32 "
        "{%0,%1,%2,%3}, {%4,%5,%6,%7}, {%8,%9}, {%0,%1,%2,%3};"
        : "+f"(c[0]), "+f"(c[1]), "+f"(c[2]), "+f"(c[3])
        : "r"(a[0]), "r"(a[1]), "r"(a[2]), "r"(a[3]), "r"(b0), "r"(b1));
}
__device__ __forceinline__ void cpa16(uint32_t dst, const void* src) {
    asm volatile("cp.async.cg.shared.global [%0], [%1], 16;" :: "r"(dst), "l"(src) : "memory");
}
#define CP_COMMIT() asm volatile("cp.async.commit_group;" ::: "memory")
#define CP_WAIT2()  asm volatile("cp.async.wait_group 2;" ::: "memory")

// smem tile layout: rows of 40 bf16 (32 data + 8 pad) = 80B stride
#define TSTR 40
#define SA_HI 0
#define SA_LO 10240
#define SB_HI 20480
#define SB_LO 30720
#define STAGE_BIG   40960   // proj/scores: A128hi/lo + B128hi/lo
#define STAGE_PV    30720   // pv: A128hi/lo + B64hi/lo

// async-load a 128-row BK=32 tile into a stage buffer
__device__ __forceinline__ void cp_tile128(uint32_t smbase, const __nv_bfloat16* src,
                                           int ld, int k0, int tid) {
    #pragma unroll
    for (int i = 0; i < 2; i++) {
        int idx = tid + i * 256;
        int r = idx >> 2, c8 = (idx & 3) << 3;
        cpa16(smbase + (uint32_t)(r * TSTR + c8) * 2, src + (size_t)r * ld + k0 + c8);
    }
}

// 3-pass (AhBh + AlBh + AhBl) 128x128 MMA over one BK=32 chunk in stage `sb`.
__device__ __forceinline__ void mma_chunk_128x128(uint32_t sb, int wm, int wn, int lane,
                                                  float acc[2][8][4]) {
    int arow = (lane & 7) + ((lane >> 3) & 1) * 8;
    int acol = (lane >> 4) * 8;
    #pragma unroll
    for (int pass = 0; pass < 3; pass++) {
        uint32_t aB = sb + ((pass == 1) ? SA_LO : SA_HI);
        uint32_t bB = sb + ((pass == 2) ? SB_LO : SB_HI);
        #pragma unroll
        for (int ks = 0; ks < 2; ks++) {
            uint32_t af[2][4];
            #pragma unroll
            for (int mi = 0; mi < 2; mi++)
                ldsm4(af[mi], aB + (uint32_t)((wm*32 + mi*16 + arow) * TSTR + ks*16 + acol) * 2);
            #pragma unroll
            for (int nb = 0; nb < 4; nb++) {
                uint32_t bt[4];
                ldsm4(bt, bB + (uint32_t)((wn*64 + nb*16 + arow) * TSTR + ks*16 + acol) * 2);
                #pragma unroll
                for (int mi = 0; mi < 2; mi++) {
                    mma16816(acc[mi][nb*2],     af[mi], bt[0], bt[2]);
                    mma16816(acc[mi][nb*2 + 1], af[mi], bt[1], bt[3]);
                }
            }
        }
    }
}

// ------------------------- conversion kernels --------------------------------
__global__ __launch_bounds__(256) void split_acts(const float* __restrict__ in, int which)
{
    __nv_bfloat16* hi = which ? g_src_hi : g_hid_hi;
    __nv_bfloat16* lo = which ? g_src_lo : g_hid_lo;
    size_t i = ((size_t)blockIdx.x * 256 + threadIdx.x) * 4;
    float4 v = *(const float4*)(in + i);
    float x[4] = {v.x, v.y, v.z, v.w};
    #pragma unroll
    for (int j = 0; j < 4; j++) {
        __nv_bfloat16 h = __float2bfloat16(x[j]);
        hi[i + j] = h;
        lo[i + j] = __float2bfloat16(x[j] - __bfloat162float(h));
    }
}

__global__ __launch_bounds__(256) void split_wt(
    const float* __restrict__ Wq, const float* __restrict__ Wk, const float* __restrict__ Wv,
    const float* __restrict__ Wq2, const float* __restrict__ Wk2)
{
    __shared__ float t[32][33];
    int w = blockIdx.z;
    const float* W = (w==0)?Wq:(w==1)?Wk:(w==2)?Wv:(w==3)?Wq2:Wk2;
    int tx = threadIdx.x & 31, ty = threadIdx.x >> 5;
    int n0 = blockIdx.x * 32, k0 = blockIdx.y * 32;
    #pragma unroll
    for (int j = 0; j < 32; j += 8)
        t[ty + j][tx] = W[(size_t)(k0 + ty + j) * Dc + n0 + tx];
    __syncthreads();
    size_t woff = (size_t)w * Dc * Dc;
    #pragma unroll
    for (int j = 0; j < 32; j += 8) {
        float x = t[tx][ty + j];
        __nv_bfloat16 h = __float2bfloat16(x);
        size_t o = woff + (size_t)(n0 + ty + j) * Dc + k0 + tx;
        g_wt_hi[o] = h;
        g_wt_lo[o] = __float2bfloat16(x - __bfloat162float(h));
    }
}

// ------------------------- projection GEMM -----------------------------------
// grid (8, 64, 5), block 256. 128x128 tile, K=1024, 4-stage cp.async pipeline.
__global__ __launch_bounds__(256) void proj_gemm(
    const float* __restrict__ bq, const float* __restrict__ bk, const float* __restrict__ bv,
    const float* __restrict__ bq2, const float* __restrict__ bk2)
{
    extern __shared__ __align__(16) char sm[];
    uint32_t smb = smem_u32(sm);
    int w = blockIdx.z, nT = blockIdx.x, mT = blockIdx.y;
    const __nv_bfloat16* Ah = ((w == 4) ? g_src_hi : g_hid_hi) + (size_t)mT * 128 * Dc;
    const __nv_bfloat16* Al = ((w == 4) ? g_src_lo : g_hid_lo) + (size_t)mT * 128 * Dc;
    size_t woff = (size_t)w * Dc * Dc + (size_t)nT * 128 * Dc;
    const __nv_bfloat16* Bh = g_wt_hi + woff;
    const __nv_bfloat16* Bl = g_wt_lo + woff;
    const float* bias = (w==0)?bq:(w==1)?bk:(w==2)?bv:(w==3)?bq2:bk2;

    int tid = threadIdx.x, lane = tid & 31, wid = tid >> 5;
    int wm = wid & 3, wn = wid >> 2;

    float acc[2][8][4];
    #pragma unroll
    for (int a = 0; a < 2; a++)
        #pragma unroll
        for (int b = 0; b < 8; b++)
            #pragma unroll
            for (int c = 0; c < 4; c++) acc[a][b][c] = 0.f;

    #pragma unroll
    for (int s = 0; s < 3; s++) {
        uint32_t sb = smb + s * STAGE_BIG;
        cp_tile128(sb + SA_HI, Ah, Dc, s*32, tid);
        cp_tile128(sb + SA_LO, Al, Dc, s*32, tid);
        cp_tile128(sb + SB_HI, Bh, Dc, s*32, tid);
        cp_tile128(sb + SB_LO, Bl, Dc, s*32, tid);
        CP_COMMIT();
    }

    for (int c = 0; c < 32; c++) {
        CP_WAIT2();
        __syncthreads();
        if (c + 3 < 32) {
            uint32_t sb = smb + ((c + 3) & 3) * STAGE_BIG;
            int kn = (c + 3) * 32;
            cp_tile128(sb + SA_HI, Ah, Dc, kn, tid);
            cp_tile128(sb + SA_LO, Al, Dc, kn, tid);
            cp_tile128(sb + SB_HI, Bh, Dc, kn, tid);
            cp_tile128(sb + SB_LO, Bl, Dc, kn, tid);
        }
        CP_COMMIT();
        mma_chunk_128x128(smb + (c & 3) * STAGE_BIG, wm, wn, lane, acc);
    }
    __syncthreads();

    // Epilogue: stage per 64-col half through smem, add bias, scatter.
    float* sf = (float*)sm;
    int mBase = mT * 128, b = mBase >> 10, l0 = mBase & 1023;
    for (int half = 0; half < 2; half++) {
        if (wn == half) {
            #pragma unroll
            for (int mi = 0; mi < 2; mi++)
                #pragma unroll
                for (int ni = 0; ni < 8; ni++) {
                    int r0 = wm*32 + mi*16 + (lane >> 2);
                    int c0 = ni*8 + (lane & 3)*2;
                    sf[r0*72 + c0]     = acc[mi][ni][0];
                    sf[r0*72 + c0 + 1] = acc[mi][ni][1];
                    sf[(r0+8)*72 + c0]     = acc[mi][ni][2];
                    sf[(r0+8)*72 + c0 + 1] = acc[mi][ni][3];
                }
        }
        __syncthreads();
        int head = nT*2 + half;
        int bh = b*16 + head;
        if (w == 2) {  // V: transpose -> vt[bh][hd][l]
            for (int idx = tid; idx < 64*128; idx += 256) {
                int hd = idx >> 7, ll = idx & 127;
                float x = sf[ll*72 + hd] + __ldg(&bias[head*64 + hd]);
                __nv_bfloat16 h = __float2bfloat16(x);
                size_t o = ((size_t)bh*64 + hd)*1024 + l0 + ll;
                g_vt_hi[o] = h;
                g_vt_lo[o] = __float2bfloat16(x - __bfloat162float(h));
            }
        } else {
            __nv_bfloat16* dhi = (w == 0 || w == 3) ? g_qq2_hi : g_kk2_hi;
            __nv_bfloat16* dlo = (w == 0 || w == 3) ? g_qq2_lo : g_kk2_lo;
            int co = (w >= 3) ? 64 : 0;
            for (int idx = tid; idx < 128*32; idx += 256) {
                int r = idx >> 5, c2 = (idx & 31)*2;
                float x0 = sf[r*72 + c2]     + __ldg(&bias[head*64 + c2]);
                float x1 = sf[r*72 + c2 + 1] + __ldg(&bias[head*64 + c2 + 1]);
                __nv_bfloat16 h0 = __float2bfloat16(x0), h1 = __float2bfloat16(x1);
                __nv_bfloat162 hp; hp.x = h0; hp.y = h1;
                __nv_bfloat162 lp;
                lp.x = __float2bfloat16(x0 - __bfloat162float(h0));
                lp.y = __float2bfloat16(x1 - __bfloat162float(h1));
                size_t o = ((size_t)bh*1024 + l0 + r)*128 + co + c2;
                *(__nv_bfloat162*)&dhi[o] = hp;
                *(__nv_bfloat162*)&dlo[o] = lp;
            }
        }
        __syncthreads();
    }
}

// ------------------------- scores GEMM ---------------------------------------
// grid (8, 8, 128), block 256. S = (QQ2 · KK2^T)*scale + mask, K=128, 4 chunks.
__global__ __launch_bounds__(256) void scores_gemm(const float* __restrict__ mask)
{
    extern __shared__ __align__(16) char sm[];
    uint32_t smb = smem_u32(sm);
    int nT = blockIdx.x, mT = blockIdx.y, bh = blockIdx.z;
    const __nv_bfloat16* Ah = g_qq2_hi + ((size_t)bh*1024 + mT*128) * 128;
    const __nv_bfloat16* Al = g_qq2_lo + ((size_t)bh*1024 + mT*128) * 128;
    const __nv_bfloat16* Bh = g_kk2_hi + ((size_t)bh*1024 + nT*128) * 128;
    const __nv_bfloat16* Bl = g_kk2_lo + ((size_t)bh*1024 + nT*128) * 128;

    int tid = threadIdx.x, lane = tid & 31, wid = tid >> 5;
    int wm = wid & 3, wn = wid >> 2;

    float acc[2][8][4];
    #pragma unroll
    for (int a = 0; a < 2; a++)
        #pragma unroll
        for (int b = 0; b < 8; b++)
            #pragma unroll
            for (int c = 0; c < 4; c++) acc[a][b][c] = 0.f;

    #pragma unroll
    for (int s = 0; s < 3; s++) {
        uint32_t sb = smb + s * STAGE_BIG;
        cp_tile128(sb + SA_HI, Ah, 128, s*32, tid);
        cp_tile128(sb + SA_LO, Al, 128, s*32, tid);
        cp_tile128(sb + SB_HI, Bh, 128, s*32, tid);
        cp_tile128(sb + SB_LO, Bl, 128, s*32, tid);
        CP_COMMIT();
    }

    #pragma unroll
    for (int c = 0; c < 4; c++) {
        CP_WAIT2();
        __syncthreads();
        if (c + 3 < 4) {
            uint32_t sb = smb + ((c + 3) & 3) * STAGE_BIG;
            int kn = (c + 3) * 32;
            cp_tile128(sb + SA_HI, Ah, 128, kn, tid);
            cp_tile128(sb + SA_LO, Al, 128, kn, tid);
            cp_tile128(sb + SB_HI, Bh, 128, kn, tid);
            cp_tile128(sb + SB_LO, Bl, 128, kn, tid);
        }
        CP_COMMIT();
        mma_chunk_128x128(smb + (c & 3) * STAGE_BIG, wm, wn, lane, acc);
    }

    int b = bh >> 4;
    size_t Srow = (size_t)bh*1024 + mT*128;
    #pragma unroll
    for (int mi = 0; mi < 2; mi++) {
        int r0 = wm*32 + mi*16 + (lane >> 2);
        #pragma unroll
        for (int ni = 0; ni < 8; ni++) {
            int c = nT*128 + wn*64 + ni*8 + (lane & 3)*2;
            float mk0 = __ldg(&mask[(size_t)b*1024 + c]);
            float mk1 = __ldg(&mask[(size_t)b*1024 + c + 1]);
            float2 v0 = make_float2(acc[mi][ni][0]*0.125f + mk0, acc[mi][ni][1]*0.125f + mk1);
            float2 v1 = make_float2(acc[mi][ni][2]*0.125f + mk0, acc[mi][ni][3]*0.125f + mk1);
            *(float2*)&g_scores[(Srow + r0)*1024 + c]     = v0;
            *(float2*)&g_scores[(Srow + r0 + 8)*1024 + c] = v1;
        }
    }
}

// ------------------------- softmax -> bf16 hi/lo probs -----------------------
__global__ __launch_bounds__(256) void softmax_split()
{
    size_t row = blockIdx.x;
    const float* p = g_scores + row * 1024;
    int tid = threadIdx.x, lane = tid & 31, wid = tid >> 5;
    __shared__ float red[8];

    float4 v = *(const float4*)&p[tid * 4];
    float m = fmaxf(fmaxf(v.x, v.y), fmaxf(v.z, v.w));
    #pragma unroll
    for (int o = 16; o > 0; o >>= 1) m = fmaxf(m, __shfl_xor_sync(0xffffffffu, m, o));
    if (lane == 0) red[wid] = m;
    __syncthreads();
    if (tid == 0) {
        float mm = red[0];
        #pragma unroll
        for (int i = 1; i < 8; i++) mm = fmaxf(mm, red[i]);
        red[0] = mm;
    }
    __syncthreads();
    m = red[0];
    __syncthreads();

    float e[4];
    e[0] = expf(v.x - m); e[1] = expf(v.y - m); e[2] = expf(v.z - m); e[3] = expf(v.w - m);
    float s = e[0] + e[1] + e[2] + e[3];
    #pragma unroll
    for (int o = 16; o > 0; o >>= 1) s += __shfl_xor_sync(0xffffffffu, s, o);
    if (lane == 0) red[wid] = s;
    __syncthreads();
    if (tid == 0) {
        float ss = red[0];
        #pragma unroll
        for (int i = 1; i < 8; i++) ss += red[i];
        red[0] = ss;
    }
    __syncthreads();
    float inv = 1.f / red[0];

    size_t o = row * 1024 + tid * 4;
    #pragma unroll
    for (int j = 0; j < 4; j += 2) {
        float x0 = e[j] * inv, x1 = e[j + 1] * inv;
        __nv_bfloat16 h0 = __float2bfloat16(x0), h1 = __float2bfloat16(x1);
        __nv_bfloat162 hp; hp.x = h0; hp.y = h1;
        __nv_bfloat162 lp;
        lp.x = __float2bfloat16(x0 - __bfloat162float(h0));
        lp.y = __float2bfloat16(x1 - __bfloat162float(h1));
        *(__nv_bfloat162*)&g_p_hi[o + j] = hp;
        *(__nv_bfloat162*)&g_p_lo[o + j] = lp;
    }
}

// ------------------------- PV GEMM -------------------------------------------
// grid (8, 128), block 256. 128x64 tile, K=1024, 4-stage cp.async pipeline.
#define PB_HI 20480
#define PB_LO 25600
__global__ __launch_bounds__(256) void pv_gemm(float* __restrict__ out)
{
    extern __shared__ __align__(16) char sm[];
    uint32_t smb = smem_u32(sm);
    int mT = blockIdx.x, bh = blockIdx.y;
    const __nv_bfloat16* Ah = g_p_hi + ((size_t)bh*1024 + mT*128) * 1024;
    const __nv_bfloat16* Al = g_p_lo + ((size_t)bh*1024 + mT*128) * 1024;
    const __nv_bfloat16* Bh = g_vt_hi + (size_t)bh*64*1024;
    const __nv_bfloat16* Bl = g_vt_lo + (size_t)bh*64*1024;

    int tid = threadIdx.x, lane = tid & 31, wm = tid >> 5;  // 8 warps over M
    int arow = (lane & 7) + ((lane >> 3) & 1) * 8;
    int acol = (lane >> 4) * 8;
    int br = tid >> 2, bc8 = (tid & 3) << 3;   // B tile: 64 rows, 1 uint4/thread

    float acc[8][4];
    #pragma unroll
    for (int b = 0; b < 8; b++)
        #pragma unroll
        for (int c = 0; c < 4; c++) acc[b][c] = 0.f;

    #pragma unroll
    for (int s = 0; s < 3; s++) {
        uint32_t sb = smb + s * STAGE_PV;
        cp_tile128(sb + SA_HI, Ah, 1024, s*32, tid);
        cp_tile128(sb + SA_LO, Al, 1024, s*32, tid);
        cpa16(sb + PB_HI + (uint32_t)(br*TSTR + bc8)*2, Bh + (size_t)br*1024 + s*32 + bc8);
        cpa16(sb + PB_LO + (uint32_t)(br*TSTR + bc8)*2, Bl + (size_t)br*1024 + s*32 + bc8);
        CP_COMMIT();
    }

    for (int k = 0; k < 32; k++) {
        CP_WAIT2();
        __syncthreads();
        if (k + 3 < 32) {
            uint32_t sb = smb + ((k + 3) & 3) * STAGE_PV;
            int kn = (k + 3) * 32;
            cp_tile128(sb + SA_HI, Ah, 1024, kn, tid);
            cp_tile128(sb + SA_LO, Al, 1024, kn, tid);
            cpa16(sb + PB_HI + (uint32_t)(br*TSTR + bc8)*2, Bh + (size_t)br*1024 + kn + bc8);
            cpa16(sb + PB_LO + (uint32_t)(br*TSTR + bc8)*2, Bl + (size_t)br*1024 + kn + bc8);
        }
        CP_COMMIT();
        uint32_t sb = smb + (k & 3) * STAGE_PV;
        #pragma unroll
        for (int pass = 0; pass < 3; pass++) {
            uint32_t aB = sb + ((pass == 1) ? SA_LO : SA_HI);
            uint32_t bB = sb + ((pass == 2) ? PB_LO : PB_HI);
            #pragma unroll
            for (int ks = 0; ks < 2; ks++) {
                uint32_t af[4];
                ldsm4(af, aB + (uint32_t)((wm*16 + arow)*TSTR + ks*16 + acol)*2);
                #pragma unroll
                for (int nb = 0; nb < 4; nb++) {
                    uint32_t bt[4];
                    ldsm4(bt, bB + (uint32_t)((nb*16 + arow)*TSTR + ks*16 + acol)*2);
                    mma16816(acc[nb*2],     af, bt[0], bt[2]);
                    mma16816(acc[nb*2 + 1], af, bt[1], bt[3]);
                }
            }
        }
    }

    int b = bh >> 4, h = bh & 15;
    int r0 = mT*128 + wm*16 + (lane >> 2);
    #pragma unroll
    for (int ni = 0; ni < 8; ni++) {
        int c = h*64 + ni*8 + (lane & 3)*2;
        *(float2*)&out[((size_t)b*1024 + r0)*1024 + c]     = make_float2(acc[ni][0], acc[ni][1]);
        *(float2*)&out[((size_t)b*1024 + r0 + 8)*1024 + c] = make_float2(acc[ni][2], acc[ni][3]);
    }
}

// ------------------------- launch --------------------------------------------
extern "C" void kernel_launch(void* const* d_in, const int* in_sizes, int n_in,
                              void* d_out, int out_size)
{
    (void)in_sizes; (void)n_in; (void)out_size;
    const float* hidden = (const float*)d_in[0];
    const float* mask   = (const float*)d_in[1];
    const float* source = (const float*)d_in[2];
    const float* bq  = (const float*)d_in[4];
    const float* bk  = (const float*)d_in[6];
    const float* bv  = (const float*)d_in[8];
    const float* bq2 = (const float*)d_in[10];
    const float* bk2 = (const float*)d_in[12];
    float* out = (float*)d_out;

    static int attr_done = 0;
    if (!attr_done) {
        cudaFuncSetAttribute(proj_gemm,   cudaFuncAttributeMaxDynamicSharedMemorySize, 4*STAGE_BIG);
        cudaFuncSetAttribute(scores_gemm, cudaFuncAttributeMaxDynamicSharedMemorySize, 4*STAGE_BIG);
        cudaFuncSetAttribute(pv_gemm,     cudaFuncAttributeMaxDynamicSharedMemorySize, 4*STAGE_PV);
        attr_done = 1;
    }

    split_acts<<<8192, 256>>>(hidden, 0);
    split_acts<<<8192, 256>>>(source, 1);
    split_wt<<<dim3(32, 32, 5), 256>>>((const float*)d_in[3], (const float*)d_in[5],
                                       (const float*)d_in[7], (const float*)d_in[9],
                                       (const float*)d_in[11]);
    proj_gemm<<<dim3(8, 64, 5), 256, 4*STAGE_BIG>>>(bq, bk, bv, bq2, bk2);
    scores_gemm<<<dim3(8, 8, 128), 256, 4*STAGE_BIG>>>(mask);
    softmax_split<<<131072, 256>>>();
    pv_gemm<<<dim3(8, 128), 256, 4*STAGE_PV>>>(out);
}

// round 10
// speedup vs baseline: 3.3324x; 1.1997x over previous
#include <cuda_runtime.h>
#include <cuda_bf16.h>
#include <stdint.h>
#include <math.h>

#define Dc 1024

// ------------------------- scratch (__device__ globals) ---------------------
__device__ __align__(128) __nv_bfloat16 g_hid_hi[8192*1024];
__device__ __align__(128) __nv_bfloat16 g_hid_lo[8192*1024];
__device__ __align__(128) __nv_bfloat16 g_src_hi[8192*1024];
__device__ __align__(128) __nv_bfloat16 g_src_lo[8192*1024];
__device__ __align__(128) __nv_bfloat16 g_wt_hi[5*1024*1024];
__device__ __align__(128) __nv_bfloat16 g_wt_lo[5*1024*1024];
__device__ __align__(128) __nv_bfloat16 g_qq2_hi[(size_t)128*1024*128];
__device__ __align__(128) __nv_bfloat16 g_qq2_lo[(size_t)128*1024*128];
__device__ __align__(128) __nv_bfloat16 g_kk2_hi[(size_t)128*1024*128];
__device__ __align__(128) __nv_bfloat16 g_kk2_lo[(size_t)128*1024*128];
__device__ __align__(128) __nv_bfloat16 g_vt_hi[(size_t)128*64*1024];
__device__ __align__(128) __nv_bfloat16 g_vt_lo[(size_t)128*64*1024];
__device__ __align__(128) __nv_bfloat16 g_p_hi[(size_t)134217728];   // unnormalized exp(S)
__device__ __align__(128) __nv_bfloat16 g_p_lo[(size_t)134217728];
__device__ __align__(128) float          g_rowpart[(size_t)128*1024*16]; // per-row partial sums

// ------------------------- warp-MMA / async helpers --------------------------
__device__ __forceinline__ uint32_t smem_u32(const void* p) {
    uint32_t a;
    asm("{ .reg .u64 t; cvta.to.shared.u64 t, %1; cvt.u32.u64 %0, t; }" : "=r"(a) : "l"(p));
    return a;
}
__device__ __forceinline__ void ldsm4(uint32_t* r, uint32_t addr) {
    asm volatile("ldmatrix.sync.aligned.m8n8.x4.shared.b16 {%0,%1,%2,%3}, [%4];"
        : "=r"(r[0]), "=r"(r[1]), "=r"(r[2]), "=r"(r[3]) : "r"(addr));
}
__device__ __forceinline__ void mma16816(float* c, const uint32_t* a, uint32_t b0, uint32_t b1) {
    asm volatile(
        "mma.sync.aligned.m16n8k16.row.col.f32.bf16.bf16.f32 "
        "{%0,%1,%2,%3}, {%4,%5,%6,%7}, {%8,%9}, {%0,%1,%2,%3};"
        : "+f"(c[0]), "+f"(c[1]), "+f"(c[2]), "+f"(c[3])
        : "r"(a[0]), "r"(a[1]), "r"(a[2]), "r"(a[3]), "r"(b0), "r"(b1));
}
__device__ __forceinline__ void cpa16(uint32_t dst, const void* src) {
    asm volatile("cp.async.cg.shared.global [%0], [%1], 16;" :: "r"(dst), "l"(src) : "memory");
}
#define CP_COMMIT() asm volatile("cp.async.commit_group;" ::: "memory")
#define CP_WAIT0()  asm volatile("cp.async.wait_group 0;" ::: "memory")

__device__ __forceinline__ void store_hilo2(__nv_bfloat16* hi, __nv_bfloat16* lo, size_t o,
                                            float x0, float x1) {
    __nv_bfloat16 h0 = __float2bfloat16(x0), h1 = __float2bfloat16(x1);
    __nv_bfloat162 hp; hp.x = h0; hp.y = h1;
    __nv_bfloat162 lp;
    lp.x = __float2bfloat16(x0 - __bfloat162float(h0));
    lp.y = __float2bfloat16(x1 - __bfloat162float(h1));
    *(__nv_bfloat162*)&hi[o] = hp;
    *(__nv_bfloat162*)&lo[o] = lp;
}

// smem tile layout: rows of 40 bf16 (32 data + 8 pad) = 80B stride
#define TSTR 40
#define SA_HI 0
#define SA_LO 10240
#define SB_HI 20480
#define SB_LO 30720
#define STAGE_BIG   40960   // proj/scores: A128hi/lo + B128hi/lo
#define STAGE_PV    30720   // pv: A128hi/lo + B64hi/lo

// async-load a 128-row BK=32 tile into a stage buffer
__device__ __forceinline__ void cp_tile128(uint32_t smbase, const __nv_bfloat16* src,
                                           int ld, int k0, int tid) {
    #pragma unroll
    for (int i = 0; i < 2; i++) {
        int idx = tid + i * 256;
        int r = idx >> 2, c8 = (idx & 3) << 3;
        cpa16(smbase + (uint32_t)(r * TSTR + c8) * 2, src + (size_t)r * ld + k0 + c8);
    }
}

// 3-pass (AhBh + AlBh + AhBl) 128x128 MMA over one BK=32 chunk in stage `sb`.
__device__ __forceinline__ void mma_chunk_128x128(uint32_t sb, int wm, int wn, int lane,
                                                  float acc[2][8][4]) {
    int arow = (lane & 7) + ((lane >> 3) & 1) * 8;
    int acol = (lane >> 4) * 8;
    #pragma unroll
    for (int pass = 0; pass < 3; pass++) {
        uint32_t aB = sb + ((pass == 1) ? SA_LO : SA_HI);
        uint32_t bB = sb + ((pass == 2) ? SB_LO : SB_HI);
        #pragma unroll
        for (int ks = 0; ks < 2; ks++) {
            uint32_t af[2][4];
            #pragma unroll
            for (int mi = 0; mi < 2; mi++)
                ldsm4(af[mi], aB + (uint32_t)((wm*32 + mi*16 + arow) * TSTR + ks*16 + acol) * 2);
            #pragma unroll
            for (int nb = 0; nb < 4; nb++) {
                uint32_t bt[4];
                ldsm4(bt, bB + (uint32_t)((wn*64 + nb*16 + arow) * TSTR + ks*16 + acol) * 2);
                #pragma unroll
                for (int mi = 0; mi < 2; mi++) {
                    mma16816(acc[mi][nb*2],     af[mi], bt[0], bt[2]);
                    mma16816(acc[mi][nb*2 + 1], af[mi], bt[1], bt[3]);
                }
            }
        }
    }
}

// ------------------------- conversion kernels --------------------------------
__global__ __launch_bounds__(256) void split_acts(const float* __restrict__ in, int which)
{
    __nv_bfloat16* hi = which ? g_src_hi : g_hid_hi;
    __nv_bfloat16* lo = which ? g_src_lo : g_hid_lo;
    size_t i = ((size_t)blockIdx.x * 256 + threadIdx.x) * 4;
    float4 v = *(const float4*)(in + i);
    float x[4] = {v.x, v.y, v.z, v.w};
    #pragma unroll
    for (int j = 0; j < 4; j++) {
        __nv_bfloat16 h = __float2bfloat16(x[j]);
        hi[i + j] = h;
        lo[i + j] = __float2bfloat16(x[j] - __bfloat162float(h));
    }
}

__global__ __launch_bounds__(256) void split_wt(
    const float* __restrict__ Wq, const float* __restrict__ Wk, const float* __restrict__ Wv,
    const float* __restrict__ Wq2, const float* __restrict__ Wk2)
{
    __shared__ float t[32][33];
    int w = blockIdx.z;
    const float* W = (w==0)?Wq:(w==1)?Wk:(w==2)?Wv:(w==3)?Wq2:Wk2;
    int tx = threadIdx.x & 31, ty = threadIdx.x >> 5;
    int n0 = blockIdx.x * 32, k0 = blockIdx.y * 32;
    #pragma unroll
    for (int j = 0; j < 32; j += 8)
        t[ty + j][tx] = W[(size_t)(k0 + ty + j) * Dc + n0 + tx];
    __syncthreads();
    size_t woff = (size_t)w * Dc * Dc;
    #pragma unroll
    for (int j = 0; j < 32; j += 8) {
        float x = t[tx][ty + j];
        __nv_bfloat16 h = __float2bfloat16(x);
        size_t o = woff + (size_t)(n0 + ty + j) * Dc + k0 + tx;
        g_wt_hi[o] = h;
        g_wt_lo[o] = __float2bfloat16(x - __bfloat162float(h));
    }
}

// ------------------------- projection GEMM -----------------------------------
// grid (8, 64, 5), block 256. 128x128 tile, K=1024. 2-stage cp.async, 2 CTA/SM.
__global__ __launch_bounds__(256, 2) void proj_gemm(
    const float* __restrict__ bq, const float* __restrict__ bk, const float* __restrict__ bv,
    const float* __restrict__ bq2, const float* __restrict__ bk2)
{
    extern __shared__ __align__(16) char sm[];
    uint32_t smb = smem_u32(sm);
    int w = blockIdx.z, nT = blockIdx.x, mT = blockIdx.y;
    const __nv_bfloat16* Ah = ((w == 4) ? g_src_hi : g_hid_hi) + (size_t)mT * 128 * Dc;
    const __nv_bfloat16* Al = ((w == 4) ? g_src_lo : g_hid_lo) + (size_t)mT * 128 * Dc;
    size_t woff = (size_t)w * Dc * Dc + (size_t)nT * 128 * Dc;
    const __nv_bfloat16* Bh = g_wt_hi + woff;
    const __nv_bfloat16* Bl = g_wt_lo + woff;
    const float* bias = (w==0)?bq:(w==1)?bk:(w==2)?bv:(w==3)?bq2:bk2;

    int tid = threadIdx.x, lane = tid & 31, wid = tid >> 5;
    int wm = wid & 3, wn = wid >> 2;

    float acc[2][8][4];
    #pragma unroll
    for (int a = 0; a < 2; a++)
        #pragma unroll
        for (int b = 0; b < 8; b++)
            #pragma unroll
            for (int c = 0; c < 4; c++) acc[a][b][c] = 0.f;

    {   // prologue: stage 0 = chunk 0
        cp_tile128(smb + SA_HI, Ah, Dc, 0, tid);
        cp_tile128(smb + SA_LO, Al, Dc, 0, tid);
        cp_tile128(smb + SB_HI, Bh, Dc, 0, tid);
        cp_tile128(smb + SB_LO, Bl, Dc, 0, tid);
        CP_COMMIT();
    }

    for (int c = 0; c < 32; c++) {
        CP_WAIT0();
        __syncthreads();
        if (c + 1 < 32) {
            uint32_t sb = smb + ((c + 1) & 1) * STAGE_BIG;
            int kn = (c + 1) * 32;
            cp_tile128(sb + SA_HI, Ah, Dc, kn, tid);
            cp_tile128(sb + SA_LO, Al, Dc, kn, tid);
            cp_tile128(sb + SB_HI, Bh, Dc, kn, tid);
            cp_tile128(sb + SB_LO, Bl, Dc, kn, tid);
            CP_COMMIT();
        }
        mma_chunk_128x128(smb + (c & 1) * STAGE_BIG, wm, wn, lane, acc);
    }
    __syncthreads();

    // Epilogue: stage per 64-col half through smem, add bias, scatter.
    float* sf = (float*)sm;
    int mBase = mT * 128, b = mBase >> 10, l0 = mBase & 1023;
    for (int half = 0; half < 2; half++) {
        if (wn == half) {
            #pragma unroll
            for (int mi = 0; mi < 2; mi++)
                #pragma unroll
                for (int ni = 0; ni < 8; ni++) {
                    int r0 = wm*32 + mi*16 + (lane >> 2);
                    int c0 = ni*8 + (lane & 3)*2;
                    sf[r0*72 + c0]     = acc[mi][ni][0];
                    sf[r0*72 + c0 + 1] = acc[mi][ni][1];
                    sf[(r0+8)*72 + c0]     = acc[mi][ni][2];
                    sf[(r0+8)*72 + c0 + 1] = acc[mi][ni][3];
                }
        }
        __syncthreads();
        int head = nT*2 + half;
        int bh = b*16 + head;
        if (w == 2) {  // V: transpose -> vt[bh][hd][l]
            for (int idx = tid; idx < 64*128; idx += 256) {
                int hd = idx >> 7, ll = idx & 127;
                float x = sf[ll*72 + hd] + __ldg(&bias[head*64 + hd]);
                __nv_bfloat16 h = __float2bfloat16(x);
                size_t o = ((size_t)bh*64 + hd)*1024 + l0 + ll;
                g_vt_hi[o] = h;
                g_vt_lo[o] = __float2bfloat16(x - __bfloat162float(h));
            }
        } else {
            __nv_bfloat16* dhi = (w == 0 || w == 3) ? g_qq2_hi : g_kk2_hi;
            __nv_bfloat16* dlo = (w == 0 || w == 3) ? g_qq2_lo : g_kk2_lo;
            int co = (w >= 3) ? 64 : 0;
            for (int idx = tid; idx < 128*32; idx += 256) {
                int r = idx >> 5, c2 = (idx & 31)*2;
                float x0 = sf[r*72 + c2]     + __ldg(&bias[head*64 + c2]);
                float x1 = sf[r*72 + c2 + 1] + __ldg(&bias[head*64 + c2 + 1]);
                store_hilo2(dhi, dlo, ((size_t)bh*1024 + l0 + r)*128 + co + c2, x0, x1);
            }
        }
        __syncthreads();
    }
}

// ------------------------- scores GEMM + exp ---------------------------------
// grid (8, 8, 128), block 256. P = exp((QQ2·KK2^T)*scale + mask) (unnormalized),
// row partial sums -> g_rowpart[row][nT*2+wn]. K=128, 2-stage cp.async.
__global__ __launch_bounds__(256, 2) void scores_gemm(const float* __restrict__ mask)
{
    extern __shared__ __align__(16) char sm[];
    uint32_t smb = smem_u32(sm);
    int nT = blockIdx.x, mT = blockIdx.y, bh = blockIdx.z;
    const __nv_bfloat16* Ah = g_qq2_hi + ((size_t)bh*1024 + mT*128) * 128;
    const __nv_bfloat16* Al = g_qq2_lo + ((size_t)bh*1024 + mT*128) * 128;
    const __nv_bfloat16* Bh = g_kk2_hi + ((size_t)bh*1024 + nT*128) * 128;
    const __nv_bfloat16* Bl = g_kk2_lo + ((size_t)bh*1024 + nT*128) * 128;

    int tid = threadIdx.x, lane = tid & 31, wid = tid >> 5;
    int wm = wid & 3, wn = wid >> 2;

    float acc[2][8][4];
    #pragma unroll
    for (int a = 0; a < 2; a++)
        #pragma unroll
        for (int b = 0; b < 8; b++)
            #pragma unroll
            for (int c = 0; c < 4; c++) acc[a][b][c] = 0.f;

    {
        cp_tile128(smb + SA_HI, Ah, 128, 0, tid);
        cp_tile128(smb + SA_LO, Al, 128, 0, tid);
        cp_tile128(smb + SB_HI, Bh, 128, 0, tid);
        cp_tile128(smb + SB_LO, Bl, 128, 0, tid);
        CP_COMMIT();
    }

    #pragma unroll
    for (int c = 0; c < 4; c++) {
        CP_WAIT0();
        __syncthreads();
        if (c + 1 < 4) {
            uint32_t sb = smb + ((c + 1) & 1) * STAGE_BIG;
            int kn = (c + 1) * 32;
            cp_tile128(sb + SA_HI, Ah, 128, kn, tid);
            cp_tile128(sb + SA_LO, Al, 128, kn, tid);
            cp_tile128(sb + SB_HI, Bh, 128, kn, tid);
            cp_tile128(sb + SB_LO, Bl, 128, kn, tid);
            CP_COMMIT();
        }
        mma_chunk_128x128(smb + (c & 1) * STAGE_BIG, wm, wn, lane, acc);
    }

    int b = bh >> 4;
    size_t Srow = (size_t)bh*1024 + mT*128;
    int slot = nT*2 + wn;
    #pragma unroll
    for (int mi = 0; mi < 2; mi++) {
        int r0 = wm*32 + mi*16 + (lane >> 2);
        float rsum0 = 0.f, rsum1 = 0.f;
        #pragma unroll
        for (int ni = 0; ni < 8; ni++) {
            int c = nT*128 + wn*64 + ni*8 + (lane & 3)*2;
            float mk0 = __ldg(&mask[(size_t)b*1024 + c]);
            float mk1 = __ldg(&mask[(size_t)b*1024 + c + 1]);
            float p0 = __expf(acc[mi][ni][0]*0.125f + mk0);
            float p1 = __expf(acc[mi][ni][1]*0.125f + mk1);
            float p2 = __expf(acc[mi][ni][2]*0.125f + mk0);
            float p3 = __expf(acc[mi][ni][3]*0.125f + mk1);
            rsum0 += p0 + p1;
            rsum1 += p2 + p3;
            store_hilo2(g_p_hi, g_p_lo, (Srow + r0)*1024 + c,     p0, p1);
            store_hilo2(g_p_hi, g_p_lo, (Srow + r0 + 8)*1024 + c, p2, p3);
        }
        rsum0 += __shfl_xor_sync(0xffffffffu, rsum0, 1);
        rsum0 += __shfl_xor_sync(0xffffffffu, rsum0, 2);
        rsum1 += __shfl_xor_sync(0xffffffffu, rsum1, 1);
        rsum1 += __shfl_xor_sync(0xffffffffu, rsum1, 2);
        if ((lane & 3) == 0) {
            g_rowpart[((Srow + r0) << 4) + slot]     = rsum0;
            g_rowpart[((Srow + r0 + 8) << 4) + slot] = rsum1;
        }
    }
}

// ------------------------- PV GEMM + normalize -------------------------------
// grid (8, 128), block 256. 128x64 tile, K=1024, 2-stage cp.async. out = (P·V)/l.
#define PB_HI 20480
#define PB_LO 25600
__global__ __launch_bounds__(256, 2) void pv_gemm(float* __restrict__ out)
{
    extern __shared__ __align__(16) char sm[];
    uint32_t smb = smem_u32(sm);
    int mT = blockIdx.x, bh = blockIdx.y;
    const __nv_bfloat16* Ah = g_p_hi + ((size_t)bh*1024 + mT*128) * 1024;
    const __nv_bfloat16* Al = g_p_lo + ((size_t)bh*1024 + mT*128) * 1024;
    const __nv_bfloat16* Bh = g_vt_hi + (size_t)bh*64*1024;
    const __nv_bfloat16* Bl = g_vt_lo + (size_t)bh*64*1024;

    int tid = threadIdx.x, lane = tid & 31, wm = tid >> 5;  // 8 warps over M
    int arow = (lane & 7) + ((lane >> 3) & 1) * 8;
    int acol = (lane >> 4) * 8;
    int br = tid >> 2, bc8 = (tid & 3) << 3;   // B tile: 64 rows, 1 uint4/thread

    float acc[8][4];
    #pragma unroll
    for (int b = 0; b < 8; b++)
        #pragma unroll
        for (int c = 0; c < 4; c++) acc[b][c] = 0.f;

    {
        cp_tile128(smb + SA_HI, Ah, 1024, 0, tid);
        cp_tile128(smb + SA_LO, Al, 1024, 0, tid);
        cpa16(smb + PB_HI + (uint32_t)(br*TSTR + bc8)*2, Bh + (size_t)br*1024 + bc8);
        cpa16(smb + PB_LO + (uint32_t)(br*TSTR + bc8)*2, Bl + (size_t)br*1024 + bc8);
        CP_COMMIT();
    }

    for (int k = 0; k < 32; k++) {
        CP_WAIT0();
        __syncthreads();
        if (k + 1 < 32) {
            uint32_t sb = smb + ((k + 1) & 1) * STAGE_PV;
            int kn = (k + 1) * 32;
            cp_tile128(sb + SA_HI, Ah, 1024, kn, tid);
            cp_tile128(sb + SA_LO, Al, 1024, kn, tid);
            cpa16(sb + PB_HI + (uint32_t)(br*TSTR + bc8)*2, Bh + (size_t)br*1024 + kn + bc8);
            cpa16(sb + PB_LO + (uint32_t)(br*TSTR + bc8)*2, Bl + (size_t)br*1024 + kn + bc8);
            CP_COMMIT();
        }
        uint32_t sb = smb + (k & 1) * STAGE_PV;
        #pragma unroll
        for (int pass = 0; pass < 3; pass++) {
            uint32_t aB = sb + ((pass == 1) ? SA_LO : SA_HI);
            uint32_t bB = sb + ((pass == 2) ? PB_LO : PB_HI);
            #pragma unroll
            for (int ks = 0; ks < 2; ks++) {
                uint32_t af[4];
                ldsm4(af, aB + (uint32_t)((wm*16 + arow)*TSTR + ks*16 + acol)*2);
                #pragma unroll
                for (int nb = 0; nb < 4; nb++) {
                    uint32_t bt[4];
                    ldsm4(bt, bB + (uint32_t)((nb*16 + arow)*TSTR + ks*16 + acol)*2);
                    mma16816(acc[nb*2],     af, bt[0], bt[2]);
                    mma16816(acc[nb*2 + 1], af, bt[1], bt[3]);
                }
            }
        }
    }

    int b = bh >> 4, h = bh & 15;
    int r0 = mT*128 + wm*16 + (lane >> 2);
    float l0 = 0.f, l1 = 0.f;
    size_t rbase0 = ((size_t)bh*1024 + r0) << 4;
    size_t rbase1 = ((size_t)bh*1024 + r0 + 8) << 4;
    #pragma unroll
    for (int j = 0; j < 16; j++) {
        l0 += g_rowpart[rbase0 + j];
        l1 += g_rowpart[rbase1 + j];
    }
    float inv0 = 1.f / l0, inv1 = 1.f / l1;
    #pragma unroll
    for (int ni = 0; ni < 8; ni++) {
        int c = h*64 + ni*8 + (lane & 3)*2;
        *(float2*)&out[((size_t)b*1024 + r0)*1024 + c] =
            make_float2(acc[ni][0]*inv0, acc[ni][1]*inv0);
        *(float2*)&out[((size_t)b*1024 + r0 + 8)*1024 + c] =
            make_float2(acc[ni][2]*inv1, acc[ni][3]*inv1);
    }
}

// ------------------------- launch --------------------------------------------
extern "C" void kernel_launch(void* const* d_in, const int* in_sizes, int n_in,
                              void* d_out, int out_size)
{
    (void)in_sizes; (void)n_in; (void)out_size;
    const float* hidden = (const float*)d_in[0];
    const float* mask   = (const float*)d_in[1];
    const float* source = (const float*)d_in[2];
    const float* bq  = (const float*)d_in[4];
    const float* bk  = (const float*)d_in[6];
    const float* bv  = (const float*)d_in[8];
    const float* bq2 = (const float*)d_in[10];
    const float* bk2 = (const float*)d_in[12];
    float* out = (float*)d_out;

    static int attr_done = 0;
    if (!attr_done) {
        cudaFuncSetAttribute(proj_gemm,   cudaFuncAttributeMaxDynamicSharedMemorySize, 2*STAGE_BIG);
        cudaFuncSetAttribute(scores_gemm, cudaFuncAttributeMaxDynamicSharedMemorySize, 2*STAGE_BIG);
        cudaFuncSetAttribute(pv_gemm,     cudaFuncAttributeMaxDynamicSharedMemorySize, 2*STAGE_PV);
        attr_done = 1;
    }

    split_acts<<<8192, 256>>>(hidden, 0);
    split_acts<<<8192, 256>>>(source, 1);
    split_wt<<<dim3(32, 32, 5), 256>>>((const float*)d_in[3], (const float*)d_in[5],
                                       (const float*)d_in[7], (const float*)d_in[9],
                                       (const float*)d_in[11]);
    proj_gemm<<<dim3(8, 64, 5), 256, 2*STAGE_BIG>>>(bq, bk, bv, bq2, bk2);
    scores_gemm<<<dim3(8, 8, 128), 256, 2*STAGE_BIG>>>(mask);
    pv_gemm<<<dim3(8, 128), 256, 2*STAGE_PV>>>(out);
}

// round 11
// speedup vs baseline: 3.5209x; 1.0565x over previous
#include <cuda_runtime.h>
#include <cuda_bf16.h>
#include <stdint.h>
#include <math.h>

#define Dc 1024

// ------------------------- scratch (__device__ globals) ---------------------
__device__ __align__(128) __nv_bfloat16 g_hid_hi[8192*1024];
__device__ __align__(128) __nv_bfloat16 g_hid_lo[8192*1024];
__device__ __align__(128) __nv_bfloat16 g_src_hi[8192*1024];
__device__ __align__(128) __nv_bfloat16 g_src_lo[8192*1024];
__device__ __align__(128) __nv_bfloat16 g_wt_hi[5*1024*1024];
__device__ __align__(128) __nv_bfloat16 g_wt_lo[5*1024*1024];
__device__ __align__(128) __nv_bfloat16 g_qq2_hi[(size_t)128*1024*128];
__device__ __align__(128) __nv_bfloat16 g_qq2_lo[(size_t)128*1024*128];
__device__ __align__(128) __nv_bfloat16 g_kk2_hi[(size_t)128*1024*128];
__device__ __align__(128) __nv_bfloat16 g_kk2_lo[(size_t)128*1024*128];
__device__ __align__(128) __nv_bfloat16 g_vt_hi[(size_t)128*64*1024];
__device__ __align__(128) __nv_bfloat16 g_vt_lo[(size_t)128*64*1024];

// ------------------------- warp-MMA / async helpers --------------------------
__device__ __forceinline__ uint32_t smem_u32(const void* p) {
    uint32_t a;
    asm("{ .reg .u64 t; cvta.to.shared.u64 t, %1; cvt.u32.u64 %0, t; }" : "=r"(a) : "l"(p));
    return a;
}
__device__ __forceinline__ void ldsm4(uint32_t* r, uint32_t addr) {
    asm volatile("ldmatrix.sync.aligned.m8n8.x4.shared.b16 {%0,%1,%2,%3}, [%4];"
        : "=r"(r[0]), "=r"(r[1]), "=r"(r[2]), "=r"(r[3]) : "r"(addr));
}
__device__ __forceinline__ void mma16816(float* c, const uint32_t* a, uint32_t b0, uint32_t b1) {
    asm volatile(
        "mma.sync.aligned.m16n8k16.row.col.f32.bf16.bf16.f32 "
        "{%0,%1,%2,%3}, {%4,%5,%6,%7}, {%8,%9}, {%0,%1,%2,%3};"
        : "+f"(c[0]), "+f"(c[1]), "+f"(c[2]), "+f"(c[3])
        : "r"(a[0]), "r"(a[1]), "r"(a[2]), "r"(a[3]), "r"(b0), "r"(b1));
}
__device__ __forceinline__ void cpa16(uint32_t dst, const void* src) {
    asm volatile("cp.async.cg.shared.global [%0], [%1], 16;" :: "r"(dst), "l"(src) : "memory");
}
#define CP_COMMIT() asm volatile("cp.async.commit_group;" ::: "memory")
#define CP_WAIT0()  asm volatile("cp.async.wait_group 0;" ::: "memory")

__device__ __forceinline__ void store_hilo2(__nv_bfloat16* hi, __nv_bfloat16* lo, size_t o,
                                            float x0, float x1) {
    __nv_bfloat16 h0 = __float2bfloat16(x0), h1 = __float2bfloat16(x1);
    __nv_bfloat162 hp; hp.x = h0; hp.y = h1;
    __nv_bfloat162 lp;
    lp.x = __float2bfloat16(x0 - __bfloat162float(h0));
    lp.y = __float2bfloat16(x1 - __bfloat162float(h1));
    *(__nv_bfloat162*)&hi[o] = hp;
    *(__nv_bfloat162*)&lo[o] = lp;
}

// smem tile layout: rows of 40 bf16 (32 data + 8 pad) = 80B stride
#define TSTR 40
#define SA_HI 0
#define SA_LO 10240
#define SB_HI 20480
#define SB_LO 30720
#define STAGE_BIG   40960

// async-load a 128-row BK=32 tile into a stage buffer
__device__ __forceinline__ void cp_tile128(uint32_t smbase, const __nv_bfloat16* src,
                                           int ld, int k0, int tid) {
    #pragma unroll
    for (int i = 0; i < 2; i++) {
        int idx = tid + i * 256;
        int r = idx >> 2, c8 = (idx & 3) << 3;
        cpa16(smbase + (uint32_t)(r * TSTR + c8) * 2, src + (size_t)r * ld + k0 + c8);
    }
}

// 3-pass (AhBh + AlBh + AhBl) 128x128 MMA over one BK=32 chunk in stage `sb`.
__device__ __forceinline__ void mma_chunk_128x128(uint32_t sb, int wm, int wn, int lane,
                                                  float acc[2][8][4]) {
    int arow = (lane & 7) + ((lane >> 3) & 1) * 8;
    int acol = (lane >> 4) * 8;
    #pragma unroll
    for (int pass = 0; pass < 3; pass++) {
        uint32_t aB = sb + ((pass == 1) ? SA_LO : SA_HI);
        uint32_t bB = sb + ((pass == 2) ? SB_LO : SB_HI);
        #pragma unroll
        for (int ks = 0; ks < 2; ks++) {
            uint32_t af[2][4];
            #pragma unroll
            for (int mi = 0; mi < 2; mi++)
                ldsm4(af[mi], aB + (uint32_t)((wm*32 + mi*16 + arow) * TSTR + ks*16 + acol) * 2);
            #pragma unroll
            for (int nb = 0; nb < 4; nb++) {
                uint32_t bt[4];
                ldsm4(bt, bB + (uint32_t)((wn*64 + nb*16 + arow) * TSTR + ks*16 + acol) * 2);
                #pragma unroll
                for (int mi = 0; mi < 2; mi++) {
                    mma16816(acc[mi][nb*2],     af[mi], bt[0], bt[2]);
                    mma16816(acc[mi][nb*2 + 1], af[mi], bt[1], bt[3]);
                }
            }
        }
    }
}

// ------------------------- conversion kernels --------------------------------
__global__ __launch_bounds__(256) void split_acts(const float* __restrict__ hid,
                                                  const float* __restrict__ src)
{
    int which = blockIdx.x >= 8192;
    const float* in = which ? src : hid;
    __nv_bfloat16* hi = which ? g_src_hi : g_hid_hi;
    __nv_bfloat16* lo = which ? g_src_lo : g_hid_lo;
    size_t i = ((size_t)(blockIdx.x & 8191) * 256 + threadIdx.x) * 4;
    float4 v = *(const float4*)(in + i);
    float x[4] = {v.x, v.y, v.z, v.w};
    #pragma unroll
    for (int j = 0; j < 4; j++) {
        __nv_bfloat16 h = __float2bfloat16(x[j]);
        hi[i + j] = h;
        lo[i + j] = __float2bfloat16(x[j] - __bfloat162float(h));
    }
}

__global__ __launch_bounds__(256) void split_wt(
    const float* __restrict__ Wq, const float* __restrict__ Wk, const float* __restrict__ Wv,
    const float* __restrict__ Wq2, const float* __restrict__ Wk2)
{
    __shared__ float t[32][33];
    int w = blockIdx.z;
    const float* W = (w==0)?Wq:(w==1)?Wk:(w==2)?Wv:(w==3)?Wq2:Wk2;
    int tx = threadIdx.x & 31, ty = threadIdx.x >> 5;
    int n0 = blockIdx.x * 32, k0 = blockIdx.y * 32;
    #pragma unroll
    for (int j = 0; j < 32; j += 8)
        t[ty + j][tx] = W[(size_t)(k0 + ty + j) * Dc + n0 + tx];
    __syncthreads();
    size_t woff = (size_t)w * Dc * Dc;
    #pragma unroll
    for (int j = 0; j < 32; j += 8) {
        float x = t[tx][ty + j];
        __nv_bfloat16 h = __float2bfloat16(x);
        size_t o = woff + (size_t)(n0 + ty + j) * Dc + k0 + tx;
        g_wt_hi[o] = h;
        g_wt_lo[o] = __float2bfloat16(x - __bfloat162float(h));
    }
}

// ------------------------- projection GEMM (unchanged from R10) --------------
__global__ __launch_bounds__(256, 2) void proj_gemm(
    const float* __restrict__ bq, const float* __restrict__ bk, const float* __restrict__ bv,
    const float* __restrict__ bq2, const float* __restrict__ bk2)
{
    extern __shared__ __align__(16) char sm[];
    uint32_t smb = smem_u32(sm);
    int w = blockIdx.z, nT = blockIdx.x, mT = blockIdx.y;
    const __nv_bfloat16* Ah = ((w == 4) ? g_src_hi : g_hid_hi) + (size_t)mT * 128 * Dc;
    const __nv_bfloat16* Al = ((w == 4) ? g_src_lo : g_hid_lo) + (size_t)mT * 128 * Dc;
    size_t woff = (size_t)w * Dc * Dc + (size_t)nT * 128 * Dc;
    const __nv_bfloat16* Bh = g_wt_hi + woff;
    const __nv_bfloat16* Bl = g_wt_lo + woff;
    const float* bias = (w==0)?bq:(w==1)?bk:(w==2)?bv:(w==3)?bq2:bk2;

    int tid = threadIdx.x, lane = tid & 31, wid = tid >> 5;
    int wm = wid & 3, wn = wid >> 2;

    float acc[2][8][4];
    #pragma unroll
    for (int a = 0; a < 2; a++)
        #pragma unroll
        for (int b = 0; b < 8; b++)
            #pragma unroll
            for (int c = 0; c < 4; c++) acc[a][b][c] = 0.f;

    cp_tile128(smb + SA_HI, Ah, Dc, 0, tid);
    cp_tile128(smb + SA_LO, Al, Dc, 0, tid);
    cp_tile128(smb + SB_HI, Bh, Dc, 0, tid);
    cp_tile128(smb + SB_LO, Bl, Dc, 0, tid);
    CP_COMMIT();

    for (int c = 0; c < 32; c++) {
        CP_WAIT0();
        __syncthreads();
        if (c + 1 < 32) {
            uint32_t sb = smb + ((c + 1) & 1) * STAGE_BIG;
            int kn = (c + 1) * 32;
            cp_tile128(sb + SA_HI, Ah, Dc, kn, tid);
            cp_tile128(sb + SA_LO, Al, Dc, kn, tid);
            cp_tile128(sb + SB_HI, Bh, Dc, kn, tid);
            cp_tile128(sb + SB_LO, Bl, Dc, kn, tid);
            CP_COMMIT();
        }
        mma_chunk_128x128(smb + (c & 1) * STAGE_BIG, wm, wn, lane, acc);
    }
    __syncthreads();

    float* sf = (float*)sm;
    int mBase = mT * 128, b = mBase >> 10, l0 = mBase & 1023;
    for (int half = 0; half < 2; half++) {
        if (wn == half) {
            #pragma unroll
            for (int mi = 0; mi < 2; mi++)
                #pragma unroll
                for (int ni = 0; ni < 8; ni++) {
                    int r0 = wm*32 + mi*16 + (lane >> 2);
                    int c0 = ni*8 + (lane & 3)*2;
                    sf[r0*72 + c0]     = acc[mi][ni][0];
                    sf[r0*72 + c0 + 1] = acc[mi][ni][1];
                    sf[(r0+8)*72 + c0]     = acc[mi][ni][2];
                    sf[(r0+8)*72 + c0 + 1] = acc[mi][ni][3];
                }
        }
        __syncthreads();
        int head = nT*2 + half;
        int bh = b*16 + head;
        if (w == 2) {
            for (int idx = tid; idx < 64*128; idx += 256) {
                int hd = idx >> 7, ll = idx & 127;
                float x = sf[ll*72 + hd] + __ldg(&bias[head*64 + hd]);
                __nv_bfloat16 h = __float2bfloat16(x);
                size_t o = ((size_t)bh*64 + hd)*1024 + l0 + ll;
                g_vt_hi[o] = h;
                g_vt_lo[o] = __float2bfloat16(x - __bfloat162float(h));
            }
        } else {
            __nv_bfloat16* dhi = (w == 0 || w == 3) ? g_qq2_hi : g_kk2_hi;
            __nv_bfloat16* dlo = (w == 0 || w == 3) ? g_qq2_lo : g_kk2_lo;
            int co = (w >= 3) ? 64 : 0;
            for (int idx = tid; idx < 128*32; idx += 256) {
                int r = idx >> 5, c2 = (idx & 31)*2;
                float x0 = sf[r*72 + c2]     + __ldg(&bias[head*64 + c2]);
                float x1 = sf[r*72 + c2 + 1] + __ldg(&bias[head*64 + c2 + 1]);
                store_hilo2(dhi, dlo, ((size_t)bh*1024 + l0 + r)*128 + co + c2, x0, x1);
            }
        }
        __syncthreads();
    }
}

// ------------------------- fused attention (scores + exp + PV) ---------------
// grid (8 mT, 128 bh), block 256, 1 CTA/SM (regs). P lives in smem only.
// smem map: [0,81920) phase-A stages (2x40960), reused as P chunks:
//   P chunk c2: hi at c2*20480, lo at c2*20480+10240
// [81920,122880) V chunks: c2*10240 (hi), +5120 (lo)
// [122880,123904) rowsum float[128][2]
#define FV_BASE  81920
#define FRS_BASE 122880
#define FUSED_SMEM 123904
__global__ __launch_bounds__(256, 1) void attn_fused(const float* __restrict__ mask,
                                                     float* __restrict__ out)
{
    extern __shared__ __align__(16) char sm[];
    uint32_t smb = smem_u32(sm);
    int mT = blockIdx.x, bh = blockIdx.y;
    int tid = threadIdx.x, lane = tid & 31, wid = tid >> 5;
    int wm = wid & 3, wn = wid >> 2;
    int b = bh >> 4, h = bh & 15;

    const __nv_bfloat16* Qh = g_qq2_hi + ((size_t)bh*1024 + mT*128) * 128;
    const __nv_bfloat16* Ql = g_qq2_lo + ((size_t)bh*1024 + mT*128) * 128;
    const __nv_bfloat16* Vh = g_vt_hi + (size_t)bh*64*1024;
    const __nv_bfloat16* Vl = g_vt_lo + (size_t)bh*64*1024;

    int arow = (lane & 7) + ((lane >> 3) & 1) * 8;
    int acol = (lane >> 4) * 8;

    float acc_o[8][4];
    #pragma unroll
    for (int i = 0; i < 8; i++)
        #pragma unroll
        for (int j = 0; j < 4; j++) acc_o[i][j] = 0.f;
    float rs[2][2] = {{0.f, 0.f}, {0.f, 0.f}};   // [mi][half] row-sum accumulators

    for (int nT = 0; nT < 8; nT++) {
        const __nv_bfloat16* Kh = g_kk2_hi + ((size_t)bh*1024 + nT*128) * 128;
        const __nv_bfloat16* Kl = g_kk2_lo + ((size_t)bh*1024 + nT*128) * 128;

        float acc_s[2][8][4];
        #pragma unroll
        for (int a = 0; a < 2; a++)
            #pragma unroll
            for (int bb = 0; bb < 8; bb++)
                #pragma unroll
                for (int c = 0; c < 4; c++) acc_s[a][bb][c] = 0.f;

        // ---- phase A: scores MMA over 4 BK=32 chunks, 2-stage pipeline ----
        cp_tile128(smb + SA_HI, Qh, 128, 0, tid);
        cp_tile128(smb + SA_LO, Ql, 128, 0, tid);
        cp_tile128(smb + SB_HI, Kh, 128, 0, tid);
        cp_tile128(smb + SB_LO, Kl, 128, 0, tid);
        CP_COMMIT();
        #pragma unroll
        for (int c = 0; c < 4; c++) {
            CP_WAIT0();
            __syncthreads();
            if (c + 1 < 4) {
                uint32_t sb = smb + ((c + 1) & 1) * STAGE_BIG;
                int kn = (c + 1) * 32;
                cp_tile128(sb + SA_HI, Qh, 128, kn, tid);
                cp_tile128(sb + SA_LO, Ql, 128, kn, tid);
                cp_tile128(sb + SB_HI, Kh, 128, kn, tid);
                cp_tile128(sb + SB_LO, Kl, 128, kn, tid);
                CP_COMMIT();
            }
            mma_chunk_128x128(smb + (c & 1) * STAGE_BIG, wm, wn, lane, acc_s);
        }
        __syncthreads();   // stages free; P region writable

        // ---- issue V chunk loads (overlap with exp/P-store) ----
        {
            int r = tid >> 2, c8 = (tid & 3) << 3;
            #pragma unroll
            for (int c2 = 0; c2 < 4; c2++) {
                const __nv_bfloat16* vsrc_h = Vh + (size_t)r*1024 + nT*128 + c2*32 + c8;
                const __nv_bfloat16* vsrc_l = Vl + (size_t)r*1024 + nT*128 + c2*32 + c8;
                cpa16(smb + FV_BASE + c2*10240 +        (uint32_t)(r*TSTR + c8)*2, vsrc_h);
                cpa16(smb + FV_BASE + c2*10240 + 5120 + (uint32_t)(r*TSTR + c8)*2, vsrc_l);
            }
            CP_COMMIT();
        }

        // ---- exp + mask + rowsum + P store (bf16 hi/lo into smem) ----
        #pragma unroll
        for (int mi = 0; mi < 2; mi++) {
            int r0 = wm*32 + mi*16 + (lane >> 2);
            float prs0 = 0.f, prs1 = 0.f;
            #pragma unroll
            for (int ni = 0; ni < 8; ni++) {
                int c = wn*64 + ni*8 + (lane & 3)*2;     // local col 0..127
                float mk0 = __ldg(&mask[(size_t)b*1024 + nT*128 + c]);
                float mk1 = __ldg(&mask[(size_t)b*1024 + nT*128 + c + 1]);
                float p0 = __expf(acc_s[mi][ni][0]*0.125f + mk0);
                float p1 = __expf(acc_s[mi][ni][1]*0.125f + mk1);
                float p2 = __expf(acc_s[mi][ni][2]*0.125f + mk0);
                float p3 = __expf(acc_s[mi][ni][3]*0.125f + mk1);
                prs0 += p0 + p1;
                prs1 += p2 + p3;
                int c2 = c >> 5, cc = c & 31;
                uint32_t base = c2*20480;
                store_hilo2((__nv_bfloat16*)(sm + base), (__nv_bfloat16*)(sm + base + 10240),
                            (size_t)(r0*TSTR + cc), p0, p1);
                store_hilo2((__nv_bfloat16*)(sm + base), (__nv_bfloat16*)(sm + base + 10240),
                            (size_t)((r0 + 8)*TSTR + cc), p2, p3);
            }
            rs[mi][0] += prs0;
            rs[mi][1] += prs1;
        }
        CP_WAIT0();        // V chunks landed
        __syncthreads();   // P visible to all warps

        // ---- phase B: PV MMA from smem (A=P chunks, B=V chunks), 3 passes ----
        #pragma unroll
        for (int c2 = 0; c2 < 4; c2++) {
            #pragma unroll
            for (int pass = 0; pass < 3; pass++) {
                uint32_t aB = smb + c2*20480 + ((pass == 1) ? 10240 : 0);
                uint32_t bB = smb + FV_BASE + c2*10240 + ((pass == 2) ? 5120 : 0);
                #pragma unroll
                for (int ks = 0; ks < 2; ks++) {
                    uint32_t af[4];
                    ldsm4(af, aB + (uint32_t)((wid*16 + arow)*TSTR + ks*16 + acol)*2);
                    #pragma unroll
                    for (int nb = 0; nb < 4; nb++) {
                        uint32_t bt[4];
                        ldsm4(bt, bB + (uint32_t)((nb*16 + arow)*TSTR + ks*16 + acol)*2);
                        mma16816(acc_o[nb*2],     af, bt[0], bt[2]);
                        mma16816(acc_o[nb*2 + 1], af, bt[1], bt[3]);
                    }
                }
            }
        }
        __syncthreads();   // P/V regions free for next nT
    }

    // ---- cross-warp row-sum exchange ----
    float* rssm = (float*)(sm + FRS_BASE);
    #pragma unroll
    for (int mi = 0; mi < 2; mi++)
        #pragma unroll
        for (int hf = 0; hf < 2; hf++) {
            float v = rs[mi][hf];
            v += __shfl_xor_sync(0xffffffffu, v, 1);
            v += __shfl_xor_sync(0xffffffffu, v, 2);
            if ((lane & 3) == 0) {
                int r = wm*32 + mi*16 + (lane >> 2) + hf*8;
                rssm[r*2 + wn] = v;
            }
        }
    __syncthreads();

    // ---- normalize + write output ----
    int rloc0 = wid*16 + (lane >> 2);
    float l0 = rssm[rloc0*2] + rssm[rloc0*2 + 1];
    float l1 = rssm[(rloc0 + 8)*2] + rssm[(rloc0 + 8)*2 + 1];
    float inv0 = 1.f / l0, inv1 = 1.f / l1;
    int r0 = mT*128 + rloc0;
    #pragma unroll
    for (int ni = 0; ni < 8; ni++) {
        int c = h*64 + ni*8 + (lane & 3)*2;
        *(float2*)&out[((size_t)b*1024 + r0)*1024 + c] =
            make_float2(acc_o[ni][0]*inv0, acc_o[ni][1]*inv0);
        *(float2*)&out[((size_t)b*1024 + r0 + 8)*1024 + c] =
            make_float2(acc_o[ni][2]*inv1, acc_o[ni][3]*inv1);
    }
}

// ------------------------- launch --------------------------------------------
extern "C" void kernel_launch(void* const* d_in, const int* in_sizes, int n_in,
                              void* d_out, int out_size)
{
    (void)in_sizes; (void)n_in; (void)out_size;
    const float* hidden = (const float*)d_in[0];
    const float* mask   = (const float*)d_in[1];
    const float* source = (const float*)d_in[2];
    const float* bq  = (const float*)d_in[4];
    const float* bk  = (const float*)d_in[6];
    const float* bv  = (const float*)d_in[8];
    const float* bq2 = (const float*)d_in[10];
    const float* bk2 = (const float*)d_in[12];
    float* out = (float*)d_out;

    static int attr_done = 0;
    if (!attr_done) {
        cudaFuncSetAttribute(proj_gemm,  cudaFuncAttributeMaxDynamicSharedMemorySize, 2*STAGE_BIG);
        cudaFuncSetAttribute(attn_fused, cudaFuncAttributeMaxDynamicSharedMemorySize, FUSED_SMEM);
        attr_done = 1;
    }

    split_acts<<<16384, 256>>>(hidden, source);
    split_wt<<<dim3(32, 32, 5), 256>>>((const float*)d_in[3], (const float*)d_in[5],
                                       (const float*)d_in[7], (const float*)d_in[9],
                                       (const float*)d_in[11]);
    proj_gemm<<<dim3(8, 64, 5), 256, 2*STAGE_BIG>>>(bq, bk, bv, bq2, bk2);
    attn_fused<<<dim3(8, 128), 256, FUSED_SMEM>>>(mask, out);
}

// round 12
// speedup vs baseline: 3.6973x; 1.0501x over previous
#include <cuda_runtime.h>
#include <cuda_bf16.h>
#include <stdint.h>
#include <math.h>

#define Dc 1024

// ------------------------- scratch (__device__ globals) ---------------------
__device__ __align__(128) __nv_bfloat16 g_hid_hi[8192*1024];
__device__ __align__(128) __nv_bfloat16 g_hid_lo[8192*1024];
__device__ __align__(128) __nv_bfloat16 g_src_hi[8192*1024];
__device__ __align__(128) __nv_bfloat16 g_src_lo[8192*1024];
__device__ __align__(128) __nv_bfloat16 g_wt_hi[5*1024*1024];
__device__ __align__(128) __nv_bfloat16 g_wt_lo[5*1024*1024];
__device__ __align__(128) __nv_bfloat16 g_qq2_hi[(size_t)128*1024*128];
__device__ __align__(128) __nv_bfloat16 g_qq2_lo[(size_t)128*1024*128];
__device__ __align__(128) __nv_bfloat16 g_kk2_hi[(size_t)128*1024*128];
__device__ __align__(128) __nv_bfloat16 g_kk2_lo[(size_t)128*1024*128];
__device__ __align__(128) __nv_bfloat16 g_vt_hi[(size_t)128*64*1024];
__device__ __align__(128) __nv_bfloat16 g_vt_lo[(size_t)128*64*1024];

// ------------------------- warp-MMA / async helpers --------------------------
__device__ __forceinline__ uint32_t smem_u32(const void* p) {
    uint32_t a;
    asm("{ .reg .u64 t; cvta.to.shared.u64 t, %1; cvt.u32.u64 %0, t; }" : "=r"(a) : "l"(p));
    return a;
}
__device__ __forceinline__ void ldsm4(uint32_t* r, uint32_t addr) {
    asm volatile("ldmatrix.sync.aligned.m8n8.x4.shared.b16 {%0,%1,%2,%3}, [%4];"
        : "=r"(r[0]), "=r"(r[1]), "=r"(r[2]), "=r"(r[3]) : "r"(addr));
}
__device__ __forceinline__ void mma16816(float* c, const uint32_t* a, uint32_t b0, uint32_t b1) {
    asm volatile(
        "mma.sync.aligned.m16n8k16.row.col.f32.bf16.bf16.f32 "
        "{%0,%1,%2,%3}, {%4,%5,%6,%7}, {%8,%9}, {%0,%1,%2,%3};"
        : "+f"(c[0]), "+f"(c[1]), "+f"(c[2]), "+f"(c[3])
        : "r"(a[0]), "r"(a[1]), "r"(a[2]), "r"(a[3]), "r"(b0), "r"(b1));
}
__device__ __forceinline__ void cpa16(uint32_t dst, const void* src) {
    asm volatile("cp.async.cg.shared.global [%0], [%1], 16;" :: "r"(dst), "l"(src) : "memory");
}
#define CP_COMMIT() asm volatile("cp.async.commit_group;" ::: "memory")
#define CP_WAIT0()  asm volatile("cp.async.wait_group 0;" ::: "memory")
#define CP_WAIT1()  asm volatile("cp.async.wait_group 1;" ::: "memory")

__device__ __forceinline__ void store_hilo2(__nv_bfloat16* hi, __nv_bfloat16* lo, size_t o,
                                            float x0, float x1) {
    __nv_bfloat16 h0 = __float2bfloat16(x0), h1 = __float2bfloat16(x1);
    __nv_bfloat162 hp; hp.x = h0; hp.y = h1;
    __nv_bfloat162 lp;
    lp.x = __float2bfloat16(x0 - __bfloat162float(h0));
    lp.y = __float2bfloat16(x1 - __bfloat162float(h1));
    *(__nv_bfloat162*)&hi[o] = hp;
    *(__nv_bfloat162*)&lo[o] = lp;
}

// smem tile layout: rows of 40 bf16 (32 data + 8 pad) = 80B stride
#define TSTR 40
#define SA_HI 0
#define SA_LO 10240
#define SB_HI 20480
#define SB_LO 30720
#define STAGE_BIG   40960

// async-load a 128-row BK=32 tile into a stage buffer
__device__ __forceinline__ void cp_tile128(uint32_t smbase, const __nv_bfloat16* src,
                                           int ld, int k0, int tid) {
    #pragma unroll
    for (int i = 0; i < 2; i++) {
        int idx = tid + i * 256;
        int r = idx >> 2, c8 = (idx & 3) << 3;
        cpa16(smbase + (uint32_t)(r * TSTR + c8) * 2, src + (size_t)r * ld + k0 + c8);
    }
}

// proj: 3-pass with A-fragment reuse (Ah shared by Bh+Bl passes). Reg-neutral.
__device__ __forceinline__ void mma_chunk_128x128(uint32_t sb, int wm, int wn, int lane,
                                                  float acc[2][8][4]) {
    int arow = (lane & 7) + ((lane >> 3) & 1) * 8;
    int acol = (lane >> 4) * 8;
    #pragma unroll
    for (int ks = 0; ks < 2; ks++) {
        uint32_t af[2][4];
        #pragma unroll
        for (int mi = 0; mi < 2; mi++)
            ldsm4(af[mi], sb + SA_HI + (uint32_t)((wm*32 + mi*16 + arow)*TSTR + ks*16 + acol)*2);
        #pragma unroll
        for (int half = 0; half < 2; half++) {          // B = hi then lo, A = hi
            uint32_t bB = sb + (half ? SB_LO : SB_HI);
            #pragma unroll
            for (int nb = 0; nb < 4; nb++) {
                uint32_t bt[4];
                ldsm4(bt, bB + (uint32_t)((wn*64 + nb*16 + arow)*TSTR + ks*16 + acol)*2);
                #pragma unroll
                for (int mi = 0; mi < 2; mi++) {
                    mma16816(acc[mi][nb*2],     af[mi], bt[0], bt[2]);
                    mma16816(acc[mi][nb*2 + 1], af[mi], bt[1], bt[3]);
                }
            }
        }
        #pragma unroll
        for (int mi = 0; mi < 2; mi++)                   // A = lo, B = hi
            ldsm4(af[mi], sb + SA_LO + (uint32_t)((wm*32 + mi*16 + arow)*TSTR + ks*16 + acol)*2);
        #pragma unroll
        for (int nb = 0; nb < 4; nb++) {
            uint32_t bt[4];
            ldsm4(bt, sb + SB_HI + (uint32_t)((wn*64 + nb*16 + arow)*TSTR + ks*16 + acol)*2);
            #pragma unroll
            for (int mi = 0; mi < 2; mi++) {
                mma16816(acc[mi][nb*2],     af[mi], bt[0], bt[2]);
                mma16816(acc[mi][nb*2 + 1], af[mi], bt[1], bt[3]);
            }
        }
    }
}

// attn phase A: fully merged (Ah+Al live, Bh shared by both) — 24 LDSM/chunk.
__device__ __forceinline__ void mma_chunk_attnA(uint32_t sb, int wm, int wn, int lane,
                                                float acc[2][8][4]) {
    int arow = (lane & 7) + ((lane >> 3) & 1) * 8;
    int acol = (lane >> 4) * 8;
    #pragma unroll
    for (int ks = 0; ks < 2; ks++) {
        uint32_t ah[2][4], al[2][4];
        #pragma unroll
        for (int mi = 0; mi < 2; mi++) {
            ldsm4(ah[mi], sb + SA_HI + (uint32_t)((wm*32 + mi*16 + arow)*TSTR + ks*16 + acol)*2);
            ldsm4(al[mi], sb + SA_LO + (uint32_t)((wm*32 + mi*16 + arow)*TSTR + ks*16 + acol)*2);
        }
        #pragma unroll
        for (int nb = 0; nb < 4; nb++) {
            uint32_t bt[4];
            ldsm4(bt, sb + SB_HI + (uint32_t)((wn*64 + nb*16 + arow)*TSTR + ks*16 + acol)*2);
            #pragma unroll
            for (int mi = 0; mi < 2; mi++) {
                mma16816(acc[mi][nb*2],     ah[mi], bt[0], bt[2]);
                mma16816(acc[mi][nb*2 + 1], ah[mi], bt[1], bt[3]);
                mma16816(acc[mi][nb*2],     al[mi], bt[0], bt[2]);
                mma16816(acc[mi][nb*2 + 1], al[mi], bt[1], bt[3]);
            }
        }
        #pragma unroll
        for (int nb = 0; nb < 4; nb++) {
            uint32_t bt[4];
            ldsm4(bt, sb + SB_LO + (uint32_t)((wn*64 + nb*16 + arow)*TSTR + ks*16 + acol)*2);
            #pragma unroll
            for (int mi = 0; mi < 2; mi++) {
                mma16816(acc[mi][nb*2],     ah[mi], bt[0], bt[2]);
                mma16816(acc[mi][nb*2 + 1], ah[mi], bt[1], bt[3]);
            }
        }
    }
}

// attn phase B: P(hi/lo) x V(hi/lo), merged — 20 LDSM/chunk.
__device__ __forceinline__ void mma_pv_chunk(uint32_t pbase, uint32_t vbase, int wid, int lane,
                                             float acc[8][4]) {
    int arow = (lane & 7) + ((lane >> 3) & 1) * 8;
    int acol = (lane >> 4) * 8;
    #pragma unroll
    for (int ks = 0; ks < 2; ks++) {
        uint32_t ah[4], al[4];
        ldsm4(ah, pbase +         (uint32_t)((wid*16 + arow)*TSTR + ks*16 + acol)*2);
        ldsm4(al, pbase + 10240 + (uint32_t)((wid*16 + arow)*TSTR + ks*16 + acol)*2);
        #pragma unroll
        for (int nb = 0; nb < 4; nb++) {
            uint32_t bt[4];
            ldsm4(bt, vbase + (uint32_t)((nb*16 + arow)*TSTR + ks*16 + acol)*2);
            mma16816(acc[nb*2],     ah, bt[0], bt[2]);
            mma16816(acc[nb*2 + 1], ah, bt[1], bt[3]);
            mma16816(acc[nb*2],     al, bt[0], bt[2]);
            mma16816(acc[nb*2 + 1], al, bt[1], bt[3]);
        }
        #pragma unroll
        for (int nb = 0; nb < 4; nb++) {
            uint32_t bt[4];
            ldsm4(bt, vbase + 5120 + (uint32_t)((nb*16 + arow)*TSTR + ks*16 + acol)*2);
            mma16816(acc[nb*2],     ah, bt[0], bt[2]);
            mma16816(acc[nb*2 + 1], ah, bt[1], bt[3]);
        }
    }
}

// ------------------------- conversion kernels --------------------------------
__global__ __launch_bounds__(256) void split_acts(const float* __restrict__ hid,
                                                  const float* __restrict__ src)
{
    int which = blockIdx.x >= 8192;
    const float* in = which ? src : hid;
    __nv_bfloat16* hi = which ? g_src_hi : g_hid_hi;
    __nv_bfloat16* lo = which ? g_src_lo : g_hid_lo;
    size_t i = ((size_t)(blockIdx.x & 8191) * 256 + threadIdx.x) * 4;
    float4 v = *(const float4*)(in + i);
    float x[4] = {v.x, v.y, v.z, v.w};
    #pragma unroll
    for (int j = 0; j < 4; j++) {
        __nv_bfloat16 h = __float2bfloat16(x[j]);
        hi[i + j] = h;
        lo[i + j] = __float2bfloat16(x[j] - __bfloat162float(h));
    }
}

__global__ __launch_bounds__(256) void split_wt(
    const float* __restrict__ Wq, const float* __restrict__ Wk, const float* __restrict__ Wv,
    const float* __restrict__ Wq2, const float* __restrict__ Wk2)
{
    __shared__ float t[32][33];
    int w = blockIdx.z;
    const float* W = (w==0)?Wq:(w==1)?Wk:(w==2)?Wv:(w==3)?Wq2:Wk2;
    int tx = threadIdx.x & 31, ty = threadIdx.x >> 5;
    int n0 = blockIdx.x * 32, k0 = blockIdx.y * 32;
    #pragma unroll
    for (int j = 0; j < 32; j += 8)
        t[ty + j][tx] = W[(size_t)(k0 + ty + j) * Dc + n0 + tx];
    __syncthreads();
    size_t woff = (size_t)w * Dc * Dc;
    #pragma unroll
    for (int j = 0; j < 32; j += 8) {
        float x = t[tx][ty + j];
        __nv_bfloat16 h = __float2bfloat16(x);
        size_t o = woff + (size_t)(n0 + ty + j) * Dc + k0 + tx;
        g_wt_hi[o] = h;
        g_wt_lo[o] = __float2bfloat16(x - __bfloat162float(h));
    }
}

// ------------------------- projection GEMM -----------------------------------
__global__ __launch_bounds__(256, 2) void proj_gemm(
    const float* __restrict__ bq, const float* __restrict__ bk, const float* __restrict__ bv,
    const float* __restrict__ bq2, const float* __restrict__ bk2)
{
    extern __shared__ __align__(16) char sm[];
    uint32_t smb = smem_u32(sm);
    int w = blockIdx.z, nT = blockIdx.x, mT = blockIdx.y;
    const __nv_bfloat16* Ah = ((w == 4) ? g_src_hi : g_hid_hi) + (size_t)mT * 128 * Dc;
    const __nv_bfloat16* Al = ((w == 4) ? g_src_lo : g_hid_lo) + (size_t)mT * 128 * Dc;
    size_t woff = (size_t)w * Dc * Dc + (size_t)nT * 128 * Dc;
    const __nv_bfloat16* Bh = g_wt_hi + woff;
    const __nv_bfloat16* Bl = g_wt_lo + woff;
    const float* bias = (w==0)?bq:(w==1)?bk:(w==2)?bv:(w==3)?bq2:bk2;

    int tid = threadIdx.x, lane = tid & 31, wid = tid >> 5;
    int wm = wid & 3, wn = wid >> 2;

    float acc[2][8][4];
    #pragma unroll
    for (int a = 0; a < 2; a++)
        #pragma unroll
        for (int b = 0; b < 8; b++)
            #pragma unroll
            for (int c = 0; c < 4; c++) acc[a][b][c] = 0.f;

    cp_tile128(smb + SA_HI, Ah, Dc, 0, tid);
    cp_tile128(smb + SA_LO, Al, Dc, 0, tid);
    cp_tile128(smb + SB_HI, Bh, Dc, 0, tid);
    cp_tile128(smb + SB_LO, Bl, Dc, 0, tid);
    CP_COMMIT();

    for (int c = 0; c < 32; c++) {
        CP_WAIT0();
        __syncthreads();
        if (c + 1 < 32) {
            uint32_t sb = smb + ((c + 1) & 1) * STAGE_BIG;
            int kn = (c + 1) * 32;
            cp_tile128(sb + SA_HI, Ah, Dc, kn, tid);
            cp_tile128(sb + SA_LO, Al, Dc, kn, tid);
            cp_tile128(sb + SB_HI, Bh, Dc, kn, tid);
            cp_tile128(sb + SB_LO, Bl, Dc, kn, tid);
            CP_COMMIT();
        }
        mma_chunk_128x128(smb + (c & 1) * STAGE_BIG, wm, wn, lane, acc);
    }
    __syncthreads();

    float* sf = (float*)sm;
    int mBase = mT * 128, b = mBase >> 10, l0 = mBase & 1023;
    for (int half = 0; half < 2; half++) {
        if (wn == half) {
            #pragma unroll
            for (int mi = 0; mi < 2; mi++)
                #pragma unroll
                for (int ni = 0; ni < 8; ni++) {
                    int r0 = wm*32 + mi*16 + (lane >> 2);
                    int c0 = ni*8 + (lane & 3)*2;
                    sf[r0*72 + c0]     = acc[mi][ni][0];
                    sf[r0*72 + c0 + 1] = acc[mi][ni][1];
                    sf[(r0+8)*72 + c0]     = acc[mi][ni][2];
                    sf[(r0+8)*72 + c0 + 1] = acc[mi][ni][3];
                }
        }
        __syncthreads();
        int head = nT*2 + half;
        int bh = b*16 + head;
        if (w == 2) {
            for (int idx = tid; idx < 64*128; idx += 256) {
                int hd = idx >> 7, ll = idx & 127;
                float x = sf[ll*72 + hd] + __ldg(&bias[head*64 + hd]);
                __nv_bfloat16 h = __float2bfloat16(x);
                size_t o = ((size_t)bh*64 + hd)*1024 + l0 + ll;
                g_vt_hi[o] = h;
                g_vt_lo[o] = __float2bfloat16(x - __bfloat162float(h));
            }
        } else {
            __nv_bfloat16* dhi = (w == 0 || w == 3) ? g_qq2_hi : g_kk2_hi;
            __nv_bfloat16* dlo = (w == 0 || w == 3) ? g_qq2_lo : g_kk2_lo;
            int co = (w >= 3) ? 64 : 0;
            for (int idx = tid; idx < 128*32; idx += 256) {
                int r = idx >> 5, c2 = (idx & 31)*2;
                float x0 = sf[r*72 + c2]     + __ldg(&bias[head*64 + c2]);
                float x1 = sf[r*72 + c2 + 1] + __ldg(&bias[head*64 + c2 + 1]);
                store_hilo2(dhi, dlo, ((size_t)bh*1024 + l0 + r)*128 + co + c2, x0, x1);
            }
        }
        __syncthreads();
    }
}

// ------------------------- fused attention -----------------------------------
// grid (8 mT, 128 bh), block 256, occ 1. 3-stage phase A, cross-nT prefetch.
// smem: stages S0/S1/S2 at i*40960 (0..122880); P reuses S0+S1; V at 122880;
// rowsums at 163840.
#define AST(i)   ((uint32_t)(i) * 40960u)
#define FV_BASE  122880
#define FRS_BASE 163840
#define FUSED_SMEM 164864
__global__ __launch_bounds__(256, 1) void attn_fused(const float* __restrict__ mask,
                                                     float* __restrict__ out)
{
    extern __shared__ __align__(16) char sm[];
    uint32_t smb = smem_u32(sm);
    int mT = blockIdx.x, bh = blockIdx.y;
    int tid = threadIdx.x, lane = tid & 31, wid = tid >> 5;
    int wm = wid & 3, wn = wid >> 2;
    int b = bh >> 4, h = bh & 15;

    const __nv_bfloat16* Qh = g_qq2_hi + ((size_t)bh*1024 + mT*128) * 128;
    const __nv_bfloat16* Ql = g_qq2_lo + ((size_t)bh*1024 + mT*128) * 128;
    const __nv_bfloat16* KhB = g_kk2_hi + (size_t)bh*1024*128;
    const __nv_bfloat16* KlB = g_kk2_lo + (size_t)bh*1024*128;
    const __nv_bfloat16* Vh = g_vt_hi + (size_t)bh*64*1024;
    const __nv_bfloat16* Vl = g_vt_lo + (size_t)bh*64*1024;

    float acc_o[8][4];
    #pragma unroll
    for (int i = 0; i < 8; i++)
        #pragma unroll
        for (int j = 0; j < 4; j++) acc_o[i][j] = 0.f;
    float rs[2][2] = {{0.f, 0.f}, {0.f, 0.f}};

    // prologue (nT=0): ch0 -> S2, ch1 -> S0 (separate groups)
    {
        const __nv_bfloat16* Kh = KhB;
        const __nv_bfloat16* Kl = KlB;
        cp_tile128(smb + AST(2) + SA_HI, Qh, 128, 0, tid);
        cp_tile128(smb + AST(2) + SA_LO, Ql, 128, 0, tid);
        cp_tile128(smb + AST(2) + SB_HI, Kh, 128, 0, tid);
        cp_tile128(smb + AST(2) + SB_LO, Kl, 128, 0, tid);
        CP_COMMIT();
        cp_tile128(smb + AST(0) + SA_HI, Qh, 128, 32, tid);
        cp_tile128(smb + AST(0) + SA_LO, Ql, 128, 32, tid);
        cp_tile128(smb + AST(0) + SB_HI, Kh, 128, 32, tid);
        cp_tile128(smb + AST(0) + SB_LO, Kl, 128, 32, tid);
        CP_COMMIT();
    }

    for (int nT = 0; nT < 8; nT++) {
        const __nv_bfloat16* Kh = KhB + (size_t)nT*128*128;
        const __nv_bfloat16* Kl = KlB + (size_t)nT*128*128;

        float acc_s[2][8][4];
        #pragma unroll
        for (int a = 0; a < 2; a++)
            #pragma unroll
            for (int bb = 0; bb < 8; bb++)
                #pragma unroll
                for (int c = 0; c < 4; c++) acc_s[a][bb][c] = 0.f;

        // phase A: chunk c -> stage (c+2)%3 ; issue c+2 at iters 0,1
        #pragma unroll
        for (int c = 0; c < 4; c++) {
            if (c < 3) { CP_WAIT1(); } else { CP_WAIT0(); }
            __syncthreads();
            if (c <= 1) {
                uint32_t sb = smb + AST((c + 1) % 3);   // stage for chunk c+2
                int kn = (c + 2) * 32;
                cp_tile128(sb + SA_HI, Qh, 128, kn, tid);
                cp_tile128(sb + SA_LO, Ql, 128, kn, tid);
                cp_tile128(sb + SB_HI, Kh, 128, kn, tid);
                cp_tile128(sb + SB_LO, Kl, 128, kn, tid);
                CP_COMMIT();
            }
            mma_chunk_attnA(smb + AST((c + 2) % 3), wm, wn, lane, acc_s);
        }
        __syncthreads();   // all warps done with stages; P region writable

        // V loads + next-nT ch0 prefetch into S2 (one group)
        {
            int r = tid >> 2, c8 = (tid & 3) << 3;
            #pragma unroll
            for (int c2 = 0; c2 < 4; c2++) {
                cpa16(smb + FV_BASE + c2*10240 +        (uint32_t)(r*TSTR + c8)*2,
                      Vh + (size_t)r*1024 + nT*128 + c2*32 + c8);
                cpa16(smb + FV_BASE + c2*10240 + 5120 + (uint32_t)(r*TSTR + c8)*2,
                      Vl + (size_t)r*1024 + nT*128 + c2*32 + c8);
            }
            if (nT < 7) {
                const __nv_bfloat16* Kh2 = KhB + (size_t)(nT+1)*128*128;
                const __nv_bfloat16* Kl2 = KlB + (size_t)(nT+1)*128*128;
                cp_tile128(smb + AST(2) + SA_HI, Qh, 128, 0, tid);
                cp_tile128(smb + AST(2) + SA_LO, Ql, 128, 0, tid);
                cp_tile128(smb + AST(2) + SB_HI, Kh2, 128, 0, tid);
                cp_tile128(smb + AST(2) + SB_LO, Kl2, 128, 0, tid);
            }
            CP_COMMIT();
        }

        // exp + mask + rowsum + P store (bf16 hi/lo into S0/S1)
        #pragma unroll
        for (int ni = 0; ni < 8; ni++) {
            int c = wn*64 + ni*8 + (lane & 3)*2;       // local col 0..127
            float mk0 = __ldg(&mask[(size_t)b*1024 + nT*128 + c]);
            float mk1 = __ldg(&mask[(size_t)b*1024 + nT*128 + c + 1]);
            int c2 = c >> 5, cc = c & 31;
            __nv_bfloat16* phi = (__nv_bfloat16*)(sm + c2*20480);
            __nv_bfloat16* plo = (__nv_bfloat16*)(sm + c2*20480 + 10240);
            #pragma unroll
            for (int mi = 0; mi < 2; mi++) {
                int r0 = wm*32 + mi*16 + (lane >> 2);
                float p0 = __expf(acc_s[mi][ni][0]*0.125f + mk0);
                float p1 = __expf(acc_s[mi][ni][1]*0.125f + mk1);
                float p2 = __expf(acc_s[mi][ni][2]*0.125f + mk0);
                float p3 = __expf(acc_s[mi][ni][3]*0.125f + mk1);
                rs[mi][0] += p0 + p1;
                rs[mi][1] += p2 + p3;
                store_hilo2(phi, plo, (size_t)(r0*TSTR + cc), p0, p1);
                store_hilo2(phi, plo, (size_t)((r0 + 8)*TSTR + cc), p2, p3);
            }
        }
        CP_WAIT0();        // V (+ next ch0) landed
        __syncthreads();   // P visible to all warps

        // phase B: PV from smem
        #pragma unroll
        for (int c2 = 0; c2 < 4; c2++)
            mma_pv_chunk(smb + c2*20480, smb + FV_BASE + c2*10240, wid, lane, acc_o);
        __syncthreads();   // P/V free

        // prologue for next nT: ch1 -> S0 (P region now free)
        if (nT < 7) {
            const __nv_bfloat16* Kh2 = KhB + (size_t)(nT+1)*128*128;
            const __nv_bfloat16* Kl2 = KlB + (size_t)(nT+1)*128*128;
            cp_tile128(smb + AST(0) + SA_HI, Qh, 128, 32, tid);
            cp_tile128(smb + AST(0) + SA_LO, Ql, 128, 32, tid);
            cp_tile128(smb + AST(0) + SB_HI, Kh2, 128, 32, tid);
            cp_tile128(smb + AST(0) + SB_LO, Kl2, 128, 32, tid);
            CP_COMMIT();
        }
    }

    // cross-warp row-sum exchange
    float* rssm = (float*)(sm + FRS_BASE);
    #pragma unroll
    for (int mi = 0; mi < 2; mi++)
        #pragma unroll
        for (int hf = 0; hf < 2; hf++) {
            float v = rs[mi][hf];
            v += __shfl_xor_sync(0xffffffffu, v, 1);
            v += __shfl_xor_sync(0xffffffffu, v, 2);
            if ((lane & 3) == 0) {
                int r = wm*32 + mi*16 + (lane >> 2) + hf*8;
                rssm[r*2 + wn] = v;
            }
        }
    __syncthreads();

    // normalize + write output
    int rloc0 = wid*16 + (lane >> 2);
    float l0 = rssm[rloc0*2] + rssm[rloc0*2 + 1];
    float l1 = rssm[(rloc0 + 8)*2] + rssm[(rloc0 + 8)*2 + 1];
    float inv0 = 1.f / l0, inv1 = 1.f / l1;
    int r0 = mT*128 + rloc0;
    #pragma unroll
    for (int ni = 0; ni < 8; ni++) {
        int c = h*64 + ni*8 + (lane & 3)*2;
        *(float2*)&out[((size_t)b*1024 + r0)*1024 + c] =
            make_float2(acc_o[ni][0]*inv0, acc_o[ni][1]*inv0);
        *(float2*)&out[((size_t)b*1024 + r0 + 8)*1024 + c] =
            make_float2(acc_o[ni][2]*inv1, acc_o[ni][3]*inv1);
    }
}

// ------------------------- launch --------------------------------------------
extern "C" void kernel_launch(void* const* d_in, const int* in_sizes, int n_in,
                              void* d_out, int out_size)
{
    (void)in_sizes; (void)n_in; (void)out_size;
    const float* hidden = (const float*)d_in[0];
    const float* mask   = (const float*)d_in[1];
    const float* source = (const float*)d_in[2];
    const float* bq  = (const float*)d_in[4];
    const float* bk  = (const float*)d_in[6];
    const float* bv  = (const float*)d_in[8];
    const float* bq2 = (const float*)d_in[10];
    const float* bk2 = (const float*)d_in[12];
    float* out = (float*)d_out;

    static int attr_done = 0;
    if (!attr_done) {
        cudaFuncSetAttribute(proj_gemm,  cudaFuncAttributeMaxDynamicSharedMemorySize, 2*STAGE_BIG);
        cudaFuncSetAttribute(attn_fused, cudaFuncAttributeMaxDynamicSharedMemorySize, FUSED_SMEM);
        attr_done = 1;
    }

    split_acts<<<16384, 256>>>(hidden, source);
    split_wt<<<dim3(32, 32, 5), 256>>>((const float*)d_in[3], (const float*)d_in[5],
                                       (const float*)d_in[7], (const float*)d_in[9],
                                       (const float*)d_in[11]);
    proj_gemm<<<dim3(8, 64, 5), 256, 2*STAGE_BIG>>>(bq, bk, bv, bq2, bk2);
    attn_fused<<<dim3(8, 128), 256, FUSED_SMEM>>>(mask, out);
}

// round 13
// speedup vs baseline: 3.7256x; 1.0077x over previous
#include <cuda_runtime.h>
#include <cuda_bf16.h>
#include <stdint.h>
#include <math.h>

#define Dc 1024

// ------------------------- scratch (__device__ globals) ---------------------
__device__ __align__(128) __nv_bfloat16 g_hid_hi[8192*1024];
__device__ __align__(128) __nv_bfloat16 g_hid_lo[8192*1024];
__device__ __align__(128) __nv_bfloat16 g_src_hi[8192*1024];
__device__ __align__(128) __nv_bfloat16 g_src_lo[8192*1024];
__device__ __align__(128) __nv_bfloat16 g_wt_hi[5*1024*1024];
__device__ __align__(128) __nv_bfloat16 g_wt_lo[5*1024*1024];
__device__ __align__(128) __nv_bfloat16 g_qq2_hi[(size_t)128*1024*128];
__device__ __align__(128) __nv_bfloat16 g_qq2_lo[(size_t)128*1024*128];
__device__ __align__(128) __nv_bfloat16 g_kk2_hi[(size_t)128*1024*128];
__device__ __align__(128) __nv_bfloat16 g_kk2_lo[(size_t)128*1024*128];
__device__ __align__(128) __nv_bfloat16 g_vt_hi[(size_t)128*64*1024];
__device__ __align__(128) __nv_bfloat16 g_vt_lo[(size_t)128*64*1024];

// ------------------------- warp-MMA / async helpers --------------------------
__device__ __forceinline__ uint32_t smem_u32(const void* p) {
    uint32_t a;
    asm("{ .reg .u64 t; cvta.to.shared.u64 t, %1; cvt.u32.u64 %0, t; }" : "=r"(a) : "l"(p));
    return a;
}
__device__ __forceinline__ void ldsm4(uint32_t* r, uint32_t addr) {
    asm volatile("ldmatrix.sync.aligned.m8n8.x4.shared.b16 {%0,%1,%2,%3}, [%4];"
        : "=r"(r[0]), "=r"(r[1]), "=r"(r[2]), "=r"(r[3]) : "r"(addr));
}
__device__ __forceinline__ void mma16816(float* c, const uint32_t* a, uint32_t b0, uint32_t b1) {
    asm volatile(
        "mma.sync.aligned.m16n8k16.row.col.f32.bf16.bf16.f32 "
        "{%0,%1,%2,%3}, {%4,%5,%6,%7}, {%8,%9}, {%0,%1,%2,%3};"
        : "+f"(c[0]), "+f"(c[1]), "+f"(c[2]), "+f"(c[3])
        : "r"(a[0]), "r"(a[1]), "r"(a[2]), "r"(a[3]), "r"(b0), "r"(b1));
}
__device__ __forceinline__ void cpa16(uint32_t dst, const void* src) {
    asm volatile("cp.async.cg.shared.global [%0], [%1], 16;" :: "r"(dst), "l"(src) : "memory");
}
#define CP_COMMIT() asm volatile("cp.async.commit_group;" ::: "memory")
#define CP_WAIT0()  asm volatile("cp.async.wait_group 0;" ::: "memory")
#define CP_WAIT1()  asm volatile("cp.async.wait_group 1;" ::: "memory")

__device__ __forceinline__ void store_hilo2(__nv_bfloat16* hi, __nv_bfloat16* lo, size_t o,
                                            float x0, float x1) {
    __nv_bfloat16 h0 = __float2bfloat16(x0), h1 = __float2bfloat16(x1);
    __nv_bfloat162 hp; hp.x = h0; hp.y = h1;
    __nv_bfloat162 lp;
    lp.x = __float2bfloat16(x0 - __bfloat162float(h0));
    lp.y = __float2bfloat16(x1 - __bfloat162float(h1));
    *(__nv_bfloat162*)&hi[o] = hp;
    *(__nv_bfloat162*)&lo[o] = lp;
}

// smem tile layout: rows of 40 bf16 (32 data + 8 pad) = 80B stride
#define TSTR 40
#define SA_HI 0
#define SA_LO 10240
#define SB_HI 20480
#define SB_LO 30720
#define STAGE_BIG   40960

// async-load a 128-row BK=32 tile into a stage buffer
__device__ __forceinline__ void cp_tile128(uint32_t smbase, const __nv_bfloat16* src,
                                           int ld, int k0, int tid) {
    #pragma unroll
    for (int i = 0; i < 2; i++) {
        int idx = tid + i * 256;
        int r = idx >> 2, c8 = (idx & 3) << 3;
        cpa16(smbase + (uint32_t)(r * TSTR + c8) * 2, src + (size_t)r * ld + k0 + c8);
    }
}

// merged 3-pass chunk (Ah+Al live, each B fragment loaded ONCE) — 24 LDSM/chunk.
// acc += Ah·Bh + Al·Bh + Ah·Bl. Used by proj AND attn phase A.
__device__ __forceinline__ void mma_chunk_attnA(uint32_t sb, int wm, int wn, int lane,
                                                float acc[2][8][4]) {
    int arow = (lane & 7) + ((lane >> 3) & 1) * 8;
    int acol = (lane >> 4) * 8;
    #pragma unroll
    for (int ks = 0; ks < 2; ks++) {
        uint32_t ah[2][4], al[2][4];
        #pragma unroll
        for (int mi = 0; mi < 2; mi++) {
            ldsm4(ah[mi], sb + SA_HI + (uint32_t)((wm*32 + mi*16 + arow)*TSTR + ks*16 + acol)*2);
            ldsm4(al[mi], sb + SA_LO + (uint32_t)((wm*32 + mi*16 + arow)*TSTR + ks*16 + acol)*2);
        }
        #pragma unroll
        for (int nb = 0; nb < 4; nb++) {
            uint32_t bt[4];
            ldsm4(bt, sb + SB_HI + (uint32_t)((wn*64 + nb*16 + arow)*TSTR + ks*16 + acol)*2);
            #pragma unroll
            for (int mi = 0; mi < 2; mi++) {
                mma16816(acc[mi][nb*2],     ah[mi], bt[0], bt[2]);
                mma16816(acc[mi][nb*2 + 1], ah[mi], bt[1], bt[3]);
                mma16816(acc[mi][nb*2],     al[mi], bt[0], bt[2]);
                mma16816(acc[mi][nb*2 + 1], al[mi], bt[1], bt[3]);
            }
        }
        #pragma unroll
        for (int nb = 0; nb < 4; nb++) {
            uint32_t bt[4];
            ldsm4(bt, sb + SB_LO + (uint32_t)((wn*64 + nb*16 + arow)*TSTR + ks*16 + acol)*2);
            #pragma unroll
            for (int mi = 0; mi < 2; mi++) {
                mma16816(acc[mi][nb*2],     ah[mi], bt[0], bt[2]);
                mma16816(acc[mi][nb*2 + 1], ah[mi], bt[1], bt[3]);
            }
        }
    }
}

// attn phase B: P(hi/lo) x V(hi/lo), merged — 20 LDSM/chunk.
__device__ __forceinline__ void mma_pv_chunk(uint32_t pbase, uint32_t vbase, int wid, int lane,
                                             float acc[8][4]) {
    int arow = (lane & 7) + ((lane >> 3) & 1) * 8;
    int acol = (lane >> 4) * 8;
    #pragma unroll
    for (int ks = 0; ks < 2; ks++) {
        uint32_t ah[4], al[4];
        ldsm4(ah, pbase +         (uint32_t)((wid*16 + arow)*TSTR + ks*16 + acol)*2);
        ldsm4(al, pbase + 10240 + (uint32_t)((wid*16 + arow)*TSTR + ks*16 + acol)*2);
        #pragma unroll
        for (int nb = 0; nb < 4; nb++) {
            uint32_t bt[4];
            ldsm4(bt, vbase + (uint32_t)((nb*16 + arow)*TSTR + ks*16 + acol)*2);
            mma16816(acc[nb*2],     ah, bt[0], bt[2]);
            mma16816(acc[nb*2 + 1], ah, bt[1], bt[3]);
            mma16816(acc[nb*2],     al, bt[0], bt[2]);
            mma16816(acc[nb*2 + 1], al, bt[1], bt[3]);
        }
        #pragma unroll
        for (int nb = 0; nb < 4; nb++) {
            uint32_t bt[4];
            ldsm4(bt, vbase + 5120 + (uint32_t)((nb*16 + arow)*TSTR + ks*16 + acol)*2);
            mma16816(acc[nb*2],     ah, bt[0], bt[2]);
            mma16816(acc[nb*2 + 1], ah, bt[1], bt[3]);
        }
    }
}

// ------------------------- conversion kernels --------------------------------
__global__ __launch_bounds__(256) void split_acts(const float* __restrict__ hid,
                                                  const float* __restrict__ src)
{
    int which = blockIdx.x >= 8192;
    const float* in = which ? src : hid;
    __nv_bfloat16* hi = which ? g_src_hi : g_hid_hi;
    __nv_bfloat16* lo = which ? g_src_lo : g_hid_lo;
    size_t i = ((size_t)(blockIdx.x & 8191) * 256 + threadIdx.x) * 4;
    float4 v = *(const float4*)(in + i);
    float x[4] = {v.x, v.y, v.z, v.w};
    #pragma unroll
    for (int j = 0; j < 4; j++) {
        __nv_bfloat16 h = __float2bfloat16(x[j]);
        hi[i + j] = h;
        lo[i + j] = __float2bfloat16(x[j] - __bfloat162float(h));
    }
}

__global__ __launch_bounds__(256) void split_wt(
    const float* __restrict__ Wq, const float* __restrict__ Wk, const float* __restrict__ Wv,
    const float* __restrict__ Wq2, const float* __restrict__ Wk2)
{
    __shared__ float t[32][33];
    int w = blockIdx.z;
    const float* W = (w==0)?Wq:(w==1)?Wk:(w==2)?Wv:(w==3)?Wq2:Wk2;
    int tx = threadIdx.x & 31, ty = threadIdx.x >> 5;
    int n0 = blockIdx.x * 32, k0 = blockIdx.y * 32;
    #pragma unroll
    for (int j = 0; j < 32; j += 8)
        t[ty + j][tx] = W[(size_t)(k0 + ty + j) * Dc + n0 + tx];
    __syncthreads();
    size_t woff = (size_t)w * Dc * Dc;
    #pragma unroll
    for (int j = 0; j < 32; j += 8) {
        float x = t[tx][ty + j];
        __nv_bfloat16 h = __float2bfloat16(x);
        size_t o = woff + (size_t)(n0 + ty + j) * Dc + k0 + tx;
        g_wt_hi[o] = h;
        g_wt_lo[o] = __float2bfloat16(x - __bfloat162float(h));
    }
}

// ------------------------- projection GEMM -----------------------------------
__global__ __launch_bounds__(256, 2) void proj_gemm(
    const float* __restrict__ bq, const float* __restrict__ bk, const float* __restrict__ bv,
    const float* __restrict__ bq2, const float* __restrict__ bk2)
{
    extern __shared__ __align__(16) char sm[];
    uint32_t smb = smem_u32(sm);
    int w = blockIdx.z, nT = blockIdx.x, mT = blockIdx.y;
    const __nv_bfloat16* Ah = ((w == 4) ? g_src_hi : g_hid_hi) + (size_t)mT * 128 * Dc;
    const __nv_bfloat16* Al = ((w == 4) ? g_src_lo : g_hid_lo) + (size_t)mT * 128 * Dc;
    size_t woff = (size_t)w * Dc * Dc + (size_t)nT * 128 * Dc;
    const __nv_bfloat16* Bh = g_wt_hi + woff;
    const __nv_bfloat16* Bl = g_wt_lo + woff;
    const float* bias = (w==0)?bq:(w==1)?bk:(w==2)?bv:(w==3)?bq2:bk2;

    int tid = threadIdx.x, lane = tid & 31, wid = tid >> 5;
    int wm = wid & 3, wn = wid >> 2;

    float acc[2][8][4];
    #pragma unroll
    for (int a = 0; a < 2; a++)
        #pragma unroll
        for (int b = 0; b < 8; b++)
            #pragma unroll
            for (int c = 0; c < 4; c++) acc[a][b][c] = 0.f;

    cp_tile128(smb + SA_HI, Ah, Dc, 0, tid);
    cp_tile128(smb + SA_LO, Al, Dc, 0, tid);
    cp_tile128(smb + SB_HI, Bh, Dc, 0, tid);
    cp_tile128(smb + SB_LO, Bl, Dc, 0, tid);
    CP_COMMIT();

    for (int c = 0; c < 32; c++) {
        CP_WAIT0();
        __syncthreads();
        if (c + 1 < 32) {
            uint32_t sb = smb + ((c + 1) & 1) * STAGE_BIG;
            int kn = (c + 1) * 32;
            cp_tile128(sb + SA_HI, Ah, Dc, kn, tid);
            cp_tile128(sb + SA_LO, Al, Dc, kn, tid);
            cp_tile128(sb + SB_HI, Bh, Dc, kn, tid);
            cp_tile128(sb + SB_LO, Bl, Dc, kn, tid);
            CP_COMMIT();
        }
        mma_chunk_attnA(smb + (c & 1) * STAGE_BIG, wm, wn, lane, acc);
    }
    __syncthreads();

    float* sf = (float*)sm;
    int mBase = mT * 128, b = mBase >> 10, l0 = mBase & 1023;
    for (int half = 0; half < 2; half++) {
        if (wn == half) {
            #pragma unroll
            for (int mi = 0; mi < 2; mi++)
                #pragma unroll
                for (int ni = 0; ni < 8; ni++) {
                    int r0 = wm*32 + mi*16 + (lane >> 2);
                    int c0 = ni*8 + (lane & 3)*2;
                    sf[r0*72 + c0]     = acc[mi][ni][0];
                    sf[r0*72 + c0 + 1] = acc[mi][ni][1];
                    sf[(r0+8)*72 + c0]     = acc[mi][ni][2];
                    sf[(r0+8)*72 + c0 + 1] = acc[mi][ni][3];
                }
        }
        __syncthreads();
        int head = nT*2 + half;
        int bh = b*16 + head;
        if (w == 2) {
            for (int idx = tid; idx < 64*128; idx += 256) {
                int hd = idx >> 7, ll = idx & 127;
                float x = sf[ll*72 + hd] + __ldg(&bias[head*64 + hd]);
                __nv_bfloat16 h = __float2bfloat16(x);
                size_t o = ((size_t)bh*64 + hd)*1024 + l0 + ll;
                g_vt_hi[o] = h;
                g_vt_lo[o] = __float2bfloat16(x - __bfloat162float(h));
            }
        } else {
            __nv_bfloat16* dhi = (w == 0 || w == 3) ? g_qq2_hi : g_kk2_hi;
            __nv_bfloat16* dlo = (w == 0 || w == 3) ? g_qq2_lo : g_kk2_lo;
            int co = (w >= 3) ? 64 : 0;
            for (int idx = tid; idx < 128*32; idx += 256) {
                int r = idx >> 5, c2 = (idx & 31)*2;
                float x0 = sf[r*72 + c2]     + __ldg(&bias[head*64 + c2]);
                float x1 = sf[r*72 + c2 + 1] + __ldg(&bias[head*64 + c2 + 1]);
                store_hilo2(dhi, dlo, ((size_t)bh*1024 + l0 + r)*128 + co + c2, x0, x1);
            }
        }
        __syncthreads();
    }
}

// ------------------------- fused attention -----------------------------------
// grid (8 mT, 128 bh), block 256, occ 1. 3-stage phase A, cross-nT prefetch.
#define AST(i)   ((uint32_t)(i) * 40960u)
#define FV_BASE  122880
#define FRS_BASE 163840
#define FUSED_SMEM 164864
__global__ __launch_bounds__(256, 1) void attn_fused(const float* __restrict__ mask,
                                                     float* __restrict__ out)
{
    extern __shared__ __align__(16) char sm[];
    uint32_t smb = smem_u32(sm);
    int mT = blockIdx.x, bh = blockIdx.y;
    int tid = threadIdx.x, lane = tid & 31, wid = tid >> 5;
    int wm = wid & 3, wn = wid >> 2;
    int b = bh >> 4, h = bh & 15;

    const __nv_bfloat16* Qh = g_qq2_hi + ((size_t)bh*1024 + mT*128) * 128;
    const __nv_bfloat16* Ql = g_qq2_lo + ((size_t)bh*1024 + mT*128) * 128;
    const __nv_bfloat16* KhB = g_kk2_hi + (size_t)bh*1024*128;
    const __nv_bfloat16* KlB = g_kk2_lo + (size_t)bh*1024*128;
    const __nv_bfloat16* Vh = g_vt_hi + (size_t)bh*64*1024;
    const __nv_bfloat16* Vl = g_vt_lo + (size_t)bh*64*1024;

    float acc_o[8][4];
    #pragma unroll
    for (int i = 0; i < 8; i++)
        #pragma unroll
        for (int j = 0; j < 4; j++) acc_o[i][j] = 0.f;
    float rs[2][2] = {{0.f, 0.f}, {0.f, 0.f}};

    // prologue (nT=0): ch0 -> S2, ch1 -> S0
    {
        cp_tile128(smb + AST(2) + SA_HI, Qh, 128, 0, tid);
        cp_tile128(smb + AST(2) + SA_LO, Ql, 128, 0, tid);
        cp_tile128(smb + AST(2) + SB_HI, KhB, 128, 0, tid);
        cp_tile128(smb + AST(2) + SB_LO, KlB, 128, 0, tid);
        CP_COMMIT();
        cp_tile128(smb + AST(0) + SA_HI, Qh, 128, 32, tid);
        cp_tile128(smb + AST(0) + SA_LO, Ql, 128, 32, tid);
        cp_tile128(smb + AST(0) + SB_HI, KhB, 128, 32, tid);
        cp_tile128(smb + AST(0) + SB_LO, KlB, 128, 32, tid);
        CP_COMMIT();
    }

    for (int nT = 0; nT < 8; nT++) {
        const __nv_bfloat16* Kh = KhB + (size_t)nT*128*128;
        const __nv_bfloat16* Kl = KlB + (size_t)nT*128*128;

        float acc_s[2][8][4];
        #pragma unroll
        for (int a = 0; a < 2; a++)
            #pragma unroll
            for (int bb = 0; bb < 8; bb++)
                #pragma unroll
                for (int c = 0; c < 4; c++) acc_s[a][bb][c] = 0.f;

        #pragma unroll
        for (int c = 0; c < 4; c++) {
            if (c < 3) { CP_WAIT1(); } else { CP_WAIT0(); }
            __syncthreads();
            if (c <= 1) {
                uint32_t sb = smb + AST((c + 1) % 3);
                int kn = (c + 2) * 32;
                cp_tile128(sb + SA_HI, Qh, 128, kn, tid);
                cp_tile128(sb + SA_LO, Ql, 128, kn, tid);
                cp_tile128(sb + SB_HI, Kh, 128, kn, tid);
                cp_tile128(sb + SB_LO, Kl, 128, kn, tid);
                CP_COMMIT();
            }
            mma_chunk_attnA(smb + AST((c + 2) % 3), wm, wn, lane, acc_s);
        }
        __syncthreads();

        // V loads + next-nT ch0 prefetch into S2
        {
            int r = tid >> 2, c8 = (tid & 3) << 3;
            #pragma unroll
            for (int c2 = 0; c2 < 4; c2++) {
                cpa16(smb + FV_BASE + c2*10240 +        (uint32_t)(r*TSTR + c8)*2,
                      Vh + (size_t)r*1024 + nT*128 + c2*32 + c8);
                cpa16(smb + FV_BASE + c2*10240 + 5120 + (uint32_t)(r*TSTR + c8)*2,
                      Vl + (size_t)r*1024 + nT*128 + c2*32 + c8);
            }
            if (nT < 7) {
                const __nv_bfloat16* Kh2 = KhB + (size_t)(nT+1)*128*128;
                const __nv_bfloat16* Kl2 = KlB + (size_t)(nT+1)*128*128;
                cp_tile128(smb + AST(2) + SA_HI, Qh, 128, 0, tid);
                cp_tile128(smb + AST(2) + SA_LO, Ql, 128, 0, tid);
                cp_tile128(smb + AST(2) + SB_HI, Kh2, 128, 0, tid);
                cp_tile128(smb + AST(2) + SB_LO, Kl2, 128, 0, tid);
            }
            CP_COMMIT();
        }

        // exp + mask + rowsum + P store
        #pragma unroll
        for (int ni = 0; ni < 8; ni++) {
            int c = wn*64 + ni*8 + (lane & 3)*2;
            float mk0 = __ldg(&mask[(size_t)b*1024 + nT*128 + c]);
            float mk1 = __ldg(&mask[(size_t)b*1024 + nT*128 + c + 1]);
            int c2 = c >> 5, cc = c & 31;
            __nv_bfloat16* phi = (__nv_bfloat16*)(sm + c2*20480);
            __nv_bfloat16* plo = (__nv_bfloat16*)(sm + c2*20480 + 10240);
            #pragma unroll
            for (int mi = 0; mi < 2; mi++) {
                int r0 = wm*32 + mi*16 + (lane >> 2);
                float p0 = __expf(acc_s[mi][ni][0]*0.125f + mk0);
                float p1 = __expf(acc_s[mi][ni][1]*0.125f + mk1);
                float p2 = __expf(acc_s[mi][ni][2]*0.125f + mk0);
                float p3 = __expf(acc_s[mi][ni][3]*0.125f + mk1);
                rs[mi][0] += p0 + p1;
                rs[mi][1] += p2 + p3;
                store_hilo2(phi, plo, (size_t)(r0*TSTR + cc), p0, p1);
                store_hilo2(phi, plo, (size_t)((r0 + 8)*TSTR + cc), p2, p3);
            }
        }
        CP_WAIT0();
        __syncthreads();

        // phase B: PV from smem
        #pragma unroll
        for (int c2 = 0; c2 < 4; c2++)
            mma_pv_chunk(smb + c2*20480, smb + FV_BASE + c2*10240, wid, lane, acc_o);
        __syncthreads();

        // prologue for next nT: ch1 -> S0
        if (nT < 7) {
            const __nv_bfloat16* Kh2 = KhB + (size_t)(nT+1)*128*128;
            const __nv_bfloat16* Kl2 = KlB + (size_t)(nT+1)*128*128;
            cp_tile128(smb + AST(0) + SA_HI, Qh, 128, 32, tid);
            cp_tile128(smb + AST(0) + SA_LO, Ql, 128, 32, tid);
            cp_tile128(smb + AST(0) + SB_HI, Kh2, 128, 32, tid);
            cp_tile128(smb + AST(0) + SB_LO, Kl2, 128, 32, tid);
            CP_COMMIT();
        }
    }

    // cross-warp row-sum exchange
    float* rssm = (float*)(sm + FRS_BASE);
    #pragma unroll
    for (int mi = 0; mi < 2; mi++)
        #pragma unroll
        for (int hf = 0; hf < 2; hf++) {
            float v = rs[mi][hf];
            v += __shfl_xor_sync(0xffffffffu, v, 1);
            v += __shfl_xor_sync(0xffffffffu, v, 2);
            if ((lane & 3) == 0) {
                int r = wm*32 + mi*16 + (lane >> 2) + hf*8;
                rssm[r*2 + wn] = v;
            }
        }
    __syncthreads();

    // normalize + write output
    int rloc0 = wid*16 + (lane >> 2);
    float l0 = rssm[rloc0*2] + rssm[rloc0*2 + 1];
    float l1 = rssm[(rloc0 + 8)*2] + rssm[(rloc0 + 8)*2 + 1];
    float inv0 = 1.f / l0, inv1 = 1.f / l1;
    int r0 = mT*128 + rloc0;
    #pragma unroll
    for (int ni = 0; ni < 8; ni++) {
        int c = h*64 + ni*8 + (lane & 3)*2;
        *(float2*)&out[((size_t)b*1024 + r0)*1024 + c] =
            make_float2(acc_o[ni][0]*inv0, acc_o[ni][1]*inv0);
        *(float2*)&out[((size_t)b*1024 + r0 + 8)*1024 + c] =
            make_float2(acc_o[ni][2]*inv1, acc_o[ni][3]*inv1);
    }
}

// ------------------------- launch --------------------------------------------
extern "C" void kernel_launch(void* const* d_in, const int* in_sizes, int n_in,
                              void* d_out, int out_size)
{
    (void)in_sizes; (void)n_in; (void)out_size;
    const float* hidden = (const float*)d_in[0];
    const float* mask   = (const float*)d_in[1];
    const float* source = (const float*)d_in[2];
    const float* bq  = (const float*)d_in[4];
    const float* bk  = (const float*)d_in[6];
    const float* bv  = (const float*)d_in[8];
    const float* bq2 = (const float*)d_in[10];
    const float* bk2 = (const float*)d_in[12];
    float* out = (float*)d_out;

    static int attr_done = 0;
    if (!attr_done) {
        cudaFuncSetAttribute(proj_gemm,  cudaFuncAttributeMaxDynamicSharedMemorySize, 2*STAGE_BIG);
        cudaFuncSetAttribute(attn_fused, cudaFuncAttributeMaxDynamicSharedMemorySize, FUSED_SMEM);
        attr_done = 1;
    }

    split_acts<<<16384, 256>>>(hidden, source);
    split_wt<<<dim3(32, 32, 5), 256>>>((const float*)d_in[3], (const float*)d_in[5],
                                       (const float*)d_in[7], (const float*)d_in[9],
                                       (const float*)d_in[11]);
    proj_gemm<<<dim3(8, 64, 5), 256, 2*STAGE_BIG>>>(bq, bk, bv, bq2, bk2);
    attn_fused<<<dim3(8, 128), 256, FUSED_SMEM>>>(mask, out);
}